// round 11
// baseline (speedup 1.0000x reference)
#include <cuda_runtime.h>
#include <cuda_fp16.h>
#include <cstdint>

// Problem constants
static constexpr int B_  = 8;
static constexpr int T_  = 2048;
static constexpr int D_  = 1024;
static constexpr int HD_ = 64;
static constexpr int M_  = B_ * T_;       // 16384 rows
static constexpr int NTOT_ = 192;         // q|k|v fused output columns
static constexpr int TK_ = 64;            // K per chunk (128B fp16 rows)
static constexpr int NCHUNK_ = D_ / TK_;  // 16

// Attention split-work constants: chunks of <=9 kt-tiles.
static constexpr int CHUNK_ = 9;
static constexpr int GPB_ = 74;           // groups per batch: sum ceil((qt+1)/9)
static constexpr int NGROUPS_ = GPB_ * B_; // 592

// Device-global scratch (fp16 hi-only; q pre-scaled by 0.125*log2e).
__device__ __align__(16) __half g_qhi[(size_t)M_ * HD_];
__device__ __align__(16) __half g_khi[(size_t)M_ * HD_];
__device__ __align__(16) __half g_vhi[(size_t)M_ * HD_];
// Pre-transposed + swizzled fp16 W-hi tiles: [chunk][n=0..191][k=0..63]
static constexpr size_t WTILE_BYTES = (size_t)NTOT_ * 128;   // 24576 per chunk
__device__ __align__(16) uint8_t g_bhi[(size_t)NCHUNK_ * WTILE_BYTES];
// Attention partials: per group O[64][64] fp32 + per row (m, l)
__device__ __align__(16) float g_pO[(size_t)NGROUPS_ * 64 * 64];
__device__ __align__(16) float g_pML[(size_t)NGROUPS_ * 64 * 2];
// Per-(b,qt) completion counters (zeroed by prep_w each launch)
__device__ int g_cnt[256];

__host__ __device__ __forceinline__ uint32_t swz128(uint32_t off) {
    return off ^ ((off >> 3) & 0x70);
}
__device__ __forceinline__ uint32_t smem_u32(const void* p) {
    uint32_t a;
    asm("{ .reg .u64 t; cvta.to.shared.u64 t, %1; cvt.u32.u64 %0, t; }"
        : "=r"(a) : "l"(p));
    return a;
}
__device__ __forceinline__ void ldsm_x4(uint32_t (&r)[4], uint32_t addr) {
    asm volatile("ldmatrix.sync.aligned.m8n8.x4.shared.b16 {%0,%1,%2,%3}, [%4];"
                 : "=r"(r[0]), "=r"(r[1]), "=r"(r[2]), "=r"(r[3]) : "r"(addr));
}
__device__ __forceinline__ void ldsm_x2(uint32_t (&r)[2], uint32_t addr) {
    asm volatile("ldmatrix.sync.aligned.m8n8.x2.shared.b16 {%0,%1}, [%2];"
                 : "=r"(r[0]), "=r"(r[1]) : "r"(addr));
}
__device__ __forceinline__ void ldsm_x4_trans(uint32_t (&r)[4], uint32_t addr) {
    asm volatile("ldmatrix.sync.aligned.m8n8.x4.trans.shared.b16 {%0,%1,%2,%3}, [%4];"
                 : "=r"(r[0]), "=r"(r[1]), "=r"(r[2]), "=r"(r[3]) : "r"(addr));
}
__device__ __forceinline__ void mma_f16(float (&d)[4], const uint32_t (&a)[4],
                                        uint32_t b0, uint32_t b1) {
    asm volatile(
        "mma.sync.aligned.m16n8k16.row.col.f32.f16.f16.f32 "
        "{%0,%1,%2,%3}, {%4,%5,%6,%7}, {%8,%9}, {%0,%1,%2,%3};"
        : "+f"(d[0]), "+f"(d[1]), "+f"(d[2]), "+f"(d[3])
        : "r"(a[0]), "r"(a[1]), "r"(a[2]), "r"(a[3]), "r"(b0), "r"(b1));
}
__device__ __forceinline__ uint32_t pack_h2(float lo, float hi) {
    __half l = __float2half_rn(lo);
    __half h = __float2half_rn(hi);
    return ((uint32_t)__half_as_ushort(h) << 16) | __half_as_ushort(l);
}
__device__ __forceinline__ uint32_t f2h2(float lo, float hi) {
    uint32_t r;
    asm("cvt.rn.f16x2.f32 %0, %1, %2;" : "=r"(r) : "f"(hi), "f"(lo));
    return r;
}
__device__ __forceinline__ uint32_t ex2h2(uint32_t x) {
    uint32_t r;
    asm("ex2.approx.f16x2 %0, %1;" : "=r"(r) : "r"(x));
    return r;
}
__device__ __forceinline__ float2 h22f2(uint32_t w) {
    __half2 h;
    *(uint32_t*)&h = w;
    return __half22float2(h);
}
__device__ __forceinline__ float ex2f(float x) {
    float y;
    asm("ex2.approx.ftz.f32 %0, %1;" : "=f"(y) : "f"(x));
    return y;
}
__device__ __forceinline__ void cp_async16(uint32_t dst, const void* src) {
    asm volatile("cp.async.ca.shared.global [%0], [%1], 16;"
                 :: "r"(dst), "l"(src));
}
#define CP_COMMIT() asm volatile("cp.async.commit_group;" ::: "memory")
#define CP_WAIT0()  asm volatile("cp.async.wait_group 0;" ::: "memory")

static constexpr float SCALE_Q = 0.125f * 1.4426950408889634f;  // 1/sqrt(64)*log2e

// ---------------------------------------------------------------------------
// Kernel 0: W -> fp16 hi (transposed, SW128 swizzled) + zero merge counters.
// ---------------------------------------------------------------------------
__global__ void prep_w_kernel(const float* __restrict__ Wq,
                              const float* __restrict__ Wk,
                              const float* __restrict__ Wv)
{
    const int th = blockIdx.x * blockDim.x + threadIdx.x;
    if (th < 256) g_cnt[th] = 0;
    if (th >= NCHUNK_ * 8 * NTOT_ * 4) return;
    const int jh = th & 3;
    const int t = th >> 2;
    const int c = t % NTOT_;
    const int rest = t / NTOT_;
    const int kg = rest % 8;
    const int chunk = rest / 8;
    const int n = c & 63;
    const float* W = (c < 64) ? Wq : (c < 128) ? Wk : Wv;
    const int k0 = chunk * TK_ + kg * 8 + jh * 2;

    const float a = W[(size_t)k0 * HD_ + n];
    const float b = W[(size_t)(k0 + 1) * HD_ + n];
    const size_t base = (size_t)chunk * WTILE_BYTES;
    const uint32_t off = swz128((uint32_t)c * 128u + (uint32_t)kg * 16u) + jh * 4u;
    *(uint32_t*)(g_bhi + base + off) = pack_h2(a, b);
}

// ---------------------------------------------------------------------------
// Kernel 1: QKV projection, mma.sync fp16 1-term. (unchanged from R10)
// ---------------------------------------------------------------------------
static constexpr int A_TILE = 64 * 128;            // 8192 bytes
static constexpr int B_TILE = NTOT_ * 128;         // 24576 bytes
static constexpr int PROJ_STAGE = A_TILE + B_TILE;       // 32768
static constexpr int PROJ_SMEM = 1024 + 2 * PROJ_STAGE;  // 66560

__global__ __launch_bounds__(256, 2) void proj_mma_kernel(const float* __restrict__ x)
{
    extern __shared__ uint8_t dynsm[];
    const uint32_t raw = smem_u32(dynsm);
    const uint32_t base = (raw + 1023u) & ~1023u;
    uint8_t* const sm = dynsm + (base - raw);

    const int tid = threadIdx.x;
    const int wid = tid >> 5;
    const int lane = tid & 31;
    const size_t row0g = (size_t)blockIdx.x * 64;

    float C[4][3][4];
#pragma unroll
    for (int mt = 0; mt < 4; mt++)
#pragma unroll
        for (int nt = 0; nt < 3; nt++)
#pragma unroll
            for (int e = 0; e < 4; e++) C[mt][nt][e] = 0.0f;

    const uint32_t a_row = (uint32_t)(lane & 15);
    const uint32_t a_kb  = (uint32_t)((lane >> 4) * 16);
    const uint32_t b_row = (uint32_t)(lane & 7);
    const uint32_t b_kb  = (uint32_t)(((lane >> 3) & 1) * 16);

    auto fillA = [&](int stage, int kc) {
        uint8_t* s = sm + stage * PROJ_STAGE;
#pragma unroll
        for (int i = 0; i < 4; i++) {
            const int idx = tid + i * 256;
            const int row = idx >> 4;
            const int c4  = idx & 15;
            float4 v = *(const float4*)&x[(row0g + row) * D_ + kc * TK_ + c4 * 4];
            const uint32_t h0 = pack_h2(v.x, v.y);
            const uint32_t h1 = pack_h2(v.z, v.w);
            const uint32_t off = swz128((uint32_t)row * 128u + (uint32_t)c4 * 8u);
            *(uint2*)(s + off) = make_uint2(h0, h1);
        }
    };
    auto cpB = [&](int stage, int kc) {
        const uint32_t sb = base + stage * PROJ_STAGE + A_TILE;
        const uint8_t* srcH = g_bhi + (size_t)kc * WTILE_BYTES;
#pragma unroll
        for (int i = 0; i < 6; i++) {
            const int idx = tid + i * 256;
            cp_async16(sb + idx * 16, srcH + idx * 16);
        }
    };

    fillA(0, 0); cpB(0, 0); CP_COMMIT(); CP_WAIT0();
    __syncthreads();

    for (int kc = 0; kc < NCHUNK_; kc++) {
        if (kc + 1 < NCHUNK_) {
            fillA((kc + 1) & 1, kc + 1);
            cpB((kc + 1) & 1, kc + 1);
            CP_COMMIT();
        }

        const uint32_t sb = base + (kc & 1) * PROJ_STAGE;
        const uint32_t sAhi = sb;
        const uint32_t sBhi = sb + A_TILE;

#pragma unroll
        for (int ks = 0; ks < 4; ks++) {
            uint32_t Ah[4][4];
#pragma unroll
            for (int mt = 0; mt < 4; mt++) {
                const uint32_t roff =
                    swz128((uint32_t)(mt * 16 + a_row) * 128u +
                           (uint32_t)ks * 32u + a_kb);
                ldsm_x4(Ah[mt], sAhi + roff);
            }
#pragma unroll
            for (int nt = 0; nt < 3; nt++) {
                const uint32_t boff =
                    swz128((uint32_t)(wid * 24 + nt * 8 + b_row) * 128u +
                           (uint32_t)ks * 32u + b_kb);
                uint32_t Bh[2];
                ldsm_x2(Bh, sBhi + boff);
#pragma unroll
                for (int mt = 0; mt < 4; mt++) {
                    mma_f16(C[mt][nt], Ah[mt], Bh[0], Bh[1]);
                }
            }
        }
        if (kc + 1 < NCHUNK_) CP_WAIT0();
        __syncthreads();
    }

#pragma unroll
    for (int mt = 0; mt < 4; mt++) {
        const size_t r = row0g + mt * 16 + (lane >> 2);
#pragma unroll
        for (int nt = 0; nt < 3; nt++) {
            const int c = wid * 24 + nt * 8 + 2 * (lane & 3);
            const int n = c & 63;
#pragma unroll
            for (int half = 0; half < 2; half++) {
                const size_t rr = r + half * 8;
                float v0 = C[mt][nt][half * 2 + 0];
                float v1 = C[mt][nt][half * 2 + 1];
                __half* o;
                if (c < 64) {
                    v0 *= SCALE_Q; v1 *= SCALE_Q;
                    o = g_qhi;
                } else {
                    o = (c < 128) ? g_khi : g_vhi;
                }
                *(uint32_t*)&o[rr * HD_ + n] = pack_h2(v0, v1);
            }
        }
    }
}

// ---------------------------------------------------------------------------
// Kernel 2: flash attention, flat chunk decomposition + fused last-CTA merge.
// s==1 qtiles write normalized output directly; s>1 groups write partials,
// bump a counter, and the last arriver merges (threadFenceReduction pattern).
// ---------------------------------------------------------------------------
static constexpr int Q_BYTES  = 64 * 128;           // 8192
static constexpr int KV_STAGE = 2 * 64 * 128;       // 16384 (khi|vhi)
static constexpr int ATTN_SMEM = 1024 + Q_BYTES + 2 * KV_STAGE;  // 41984

__global__ __launch_bounds__(128, 4) void attn_mma_kernel(float* __restrict__ out)
{
    extern __shared__ uint8_t dynsm[];
    const uint32_t raw = smem_u32(dynsm);
    const uint32_t base = (raw + 1023u) & ~1023u;
    __shared__ int sOld;

    const int tid = threadIdx.x;
    const int wi  = tid >> 5;
    const int lane = tid & 31;

    // ---- decode work item: batch, q-tile, kt chunk ----
    const int bid = blockIdx.x;
    const int b = bid / GPB_;
    int r = bid % GPB_;
    int qt = 31, s = 4;
    for (qt = 31; qt >= 0; qt--) {
        s = (qt + CHUNK_) / CHUNK_;
        if (r < s) break;
        r -= s;
    }
    const int n = qt + 1;
    const int cbase = n / s, crem = n % s;
    const int kt0 = r * cbase + (r < crem ? r : crem);
    const int niter = cbase + (r < crem ? 1 : 0);

    const uint32_t sQ  = base;
    const uint32_t sKV = base + Q_BYTES;
    const size_t qrow0 = (size_t)b * T_ + (size_t)qt * 64;

#pragma unroll
    for (int i = 0; i < 4; i++) {
        const int idx = tid + i * 128;
        const int row = idx >> 3;
        const int c16 = idx & 7;
        const uint32_t doff = swz128((uint32_t)row * 128u + (uint32_t)c16 * 16u);
        cp_async16(sQ + doff, &g_qhi[(qrow0 + row) * HD_ + c16 * 8]);
    }
    CP_COMMIT();

    auto prefetch_kv = [&](int kt, int stage) {
        const uint32_t sb = sKV + stage * KV_STAGE;
        const size_t krow0 = (size_t)b * T_ + (size_t)kt * 64;
#pragma unroll
        for (int i = 0; i < 8; i++) {
            const int idx = tid + i * 128;
            const int arr = idx >> 9;
            const int row = (idx >> 3) & 63;
            const int c16 = idx & 7;
            const uint32_t doff = swz128((uint32_t)row * 128u + (uint32_t)c16 * 16u);
            const __half* src = arr ? g_vhi : g_khi;
            cp_async16(sb + arr * 8192 + doff, &src[(krow0 + row) * HD_ + c16 * 8]);
        }
    };
    prefetch_kv(kt0, 0);
    CP_COMMIT();
    CP_WAIT0();
    __syncthreads();

    uint32_t Qh[4][4];
    {
        const uint32_t a_row = (uint32_t)(lane & 15);
        const uint32_t a_kb  = (uint32_t)((lane >> 4) * 16);
#pragma unroll
        for (int ks = 0; ks < 4; ks++) {
            const uint32_t roff =
                swz128((uint32_t)(wi * 16 + a_row) * 128u + (uint32_t)ks * 32u + a_kb);
            ldsm_x4(Qh[ks], sQ + roff);
        }
    }

    float O[8][4];
#pragma unroll
    for (int nh = 0; nh < 8; nh++)
#pragma unroll
        for (int e = 0; e < 4; e++) O[nh][e] = 0.0f;
    float m0 = -1e30f, m1 = -1e30f, l0 = 0.0f, l1 = 0.0f;

    const int kg  = lane >> 3;
    const uint32_t k_row8 = (uint32_t)(lane & 7);
    const uint32_t k_rowsel = (uint32_t)(kg >> 1) * 8;
    const uint32_t k_kb = (uint32_t)(kg & 1) * 16;
    const uint32_t v_rowsel = (uint32_t)(kg & 1) * 8;
    const uint32_t v_colsel = (uint32_t)(kg >> 1) * 16;
    const int q2 = 2 * (lane & 3);
    const int rloc = (lane >> 2);

    for (int i = 0; i < niter; i++) {
        if (i + 1 < niter) prefetch_kv(kt0 + i + 1, (i + 1) & 1);
        CP_COMMIT();

        const int kt = kt0 + i;
        const uint32_t sb = sKV + (i & 1) * KV_STAGE;
        const uint32_t sKh = sb;
        const uint32_t sVh = sb + 8192;

        float S[8][4];
#pragma unroll
        for (int nt = 0; nt < 8; nt++)
#pragma unroll
            for (int e = 0; e < 4; e++) S[nt][e] = 0.0f;

#pragma unroll
        for (int ks = 0; ks < 4; ks++) {
#pragma unroll
            for (int ntp = 0; ntp < 4; ntp++) {
                const uint32_t boff =
                    swz128((uint32_t)(ntp * 16 + k_rowsel + k_row8) * 128u +
                           (uint32_t)ks * 32u + k_kb);
                uint32_t Kf[4];
                ldsm_x4(Kf, sKh + boff);
                mma_f16(S[2 * ntp],     Qh[ks], Kf[0], Kf[1]);
                mma_f16(S[2 * ntp + 1], Qh[ks], Kf[2], Kf[3]);
            }
        }

        if (kt == qt) {
            const int r0 = wi * 16 + rloc;
#pragma unroll
            for (int nt = 0; nt < 8; nt++) {
                const int c0 = nt * 8 + q2;
                if (c0 > r0)     S[nt][0] = -1e30f;
                if (c0 + 1 > r0) S[nt][1] = -1e30f;
                if (c0 > r0 + 8)     S[nt][2] = -1e30f;
                if (c0 + 1 > r0 + 8) S[nt][3] = -1e30f;
            }
        }

        float mx0 = -1e30f, mx1 = -1e30f;
#pragma unroll
        for (int nt = 0; nt < 8; nt++) {
            mx0 = fmaxf(mx0, fmaxf(S[nt][0], S[nt][1]));
            mx1 = fmaxf(mx1, fmaxf(S[nt][2], S[nt][3]));
        }
        mx0 = fmaxf(mx0, __shfl_xor_sync(0xffffffffu, mx0, 1));
        mx0 = fmaxf(mx0, __shfl_xor_sync(0xffffffffu, mx0, 2));
        mx1 = fmaxf(mx1, __shfl_xor_sync(0xffffffffu, mx1, 1));
        mx1 = fmaxf(mx1, __shfl_xor_sync(0xffffffffu, mx1, 2));
        const float mn0 = fmaxf(m0, mx0);
        const float mn1 = fmaxf(m1, mx1);
        const float a0 = ex2f(m0 - mn0);
        const float a1 = ex2f(m1 - mn1);
        m0 = mn0; m1 = mn1;

        uint32_t P[4][4];
        float sum0 = 0.0f, sum1 = 0.0f;
#pragma unroll
        for (int nt = 0; nt < 8; nt++) {
            const uint32_t w01 = ex2h2(f2h2(S[nt][0] - mn0, S[nt][1] - mn0));
            const uint32_t w23 = ex2h2(f2h2(S[nt][2] - mn1, S[nt][3] - mn1));
            P[nt >> 1][(nt & 1) * 2 + 0] = w01;
            P[nt >> 1][(nt & 1) * 2 + 1] = w23;
            const float2 f01 = h22f2(w01);
            const float2 f23 = h22f2(w23);
            sum0 += f01.x + f01.y;
            sum1 += f23.x + f23.y;
        }
        sum0 += __shfl_xor_sync(0xffffffffu, sum0, 1);
        sum0 += __shfl_xor_sync(0xffffffffu, sum0, 2);
        sum1 += __shfl_xor_sync(0xffffffffu, sum1, 1);
        sum1 += __shfl_xor_sync(0xffffffffu, sum1, 2);
        l0 = l0 * a0 + sum0;
        l1 = l1 * a1 + sum1;

#pragma unroll
        for (int nh = 0; nh < 8; nh++) {
            O[nh][0] *= a0; O[nh][1] *= a0;
            O[nh][2] *= a1; O[nh][3] *= a1;
        }

#pragma unroll
        for (int t = 0; t < 4; t++) {
#pragma unroll
            for (int nhp = 0; nhp < 4; nhp++) {
                const uint32_t voff =
                    swz128((uint32_t)(t * 16 + v_rowsel + k_row8) * 128u +
                           (uint32_t)nhp * 32u + v_colsel);
                uint32_t Vf[4];
                ldsm_x4_trans(Vf, sVh + voff);
                mma_f16(O[2 * nhp],     P[t], Vf[0], Vf[1]);
                mma_f16(O[2 * nhp + 1], P[t], Vf[2], Vf[3]);
            }
        }

        CP_WAIT0();
        __syncthreads();
    }

    const int row0 = wi * 16 + rloc;

    if (s == 1) {
        // ---- single-chunk qtile: normalize and store directly ----
        const float il0 = 1.0f / l0;
        const float il1 = 1.0f / l1;
        const size_t grow = qrow0 + (size_t)row0;
#pragma unroll
        for (int nh = 0; nh < 8; nh++) {
            const int hcol = nh * 8 + q2;
            *(float2*)&out[grow * HD_ + hcol] =
                make_float2(O[nh][0] * il0, O[nh][1] * il0);
            *(float2*)&out[(grow + 8) * HD_ + hcol] =
                make_float2(O[nh][2] * il1, O[nh][3] * il1);
        }
        return;
    }

    // ---- write partials to gmem ----
    float* const pO = g_pO + (size_t)bid * 4096;
    if ((lane & 3) == 0) {
        float* const pml = g_pML + (size_t)bid * 128;
        *(float2*)&pml[row0 * 2]       = make_float2(m0, l0);
        *(float2*)&pml[(row0 + 8) * 2] = make_float2(m1, l1);
    }
#pragma unroll
    for (int nh = 0; nh < 8; nh++) {
        const int hcol = nh * 8 + q2;
        *(float2*)&pO[row0 * 64 + hcol]       = make_float2(O[nh][0], O[nh][1]);
        *(float2*)&pO[(row0 + 8) * 64 + hcol] = make_float2(O[nh][2], O[nh][3]);
    }

    // ---- last CTA for this qtile merges ----
    __threadfence();
    if (tid == 0) sOld = atomicAdd(&g_cnt[(b << 5) + qt], 1);
    __syncthreads();
    if (sOld != s - 1) return;

    const int g0 = bid - r;           // first group of this qtile
    const int row = tid >> 1;         // 0..63
    const int hc  = (tid & 1) * 32;   // 0 or 32

    float mp[4], lp[4];
    float M = -1e30f;
#pragma unroll 4
    for (int p = 0; p < s; p++) {
        const float2 ml = *(const float2*)&g_pML[(size_t)(g0 + p) * 128 + row * 2];
        mp[p] = ml.x; lp[p] = ml.y;
        M = fmaxf(M, ml.x);
    }
    float w[4];
    float L = 0.0f;
#pragma unroll 4
    for (int p = 0; p < s; p++) {
        w[p] = ex2f(mp[p] - M);
        L += lp[p] * w[p];
    }
    const float invL = 1.0f / L;

    const size_t orow = (qrow0 + (size_t)row) * HD_ + hc;
#pragma unroll
    for (int c4 = 0; c4 < 32; c4 += 8) {
        float4 acc0 = make_float4(0.f, 0.f, 0.f, 0.f);
        float4 acc1 = make_float4(0.f, 0.f, 0.f, 0.f);
#pragma unroll 4
        for (int p = 0; p < s; p++) {
            const float* src = &g_pO[(size_t)(g0 + p) * 4096 + row * 64 + hc + c4];
            const float4 v0 = *(const float4*)&src[0];
            const float4 v1 = *(const float4*)&src[4];
            acc0.x += v0.x * w[p]; acc0.y += v0.y * w[p];
            acc0.z += v0.z * w[p]; acc0.w += v0.w * w[p];
            acc1.x += v1.x * w[p]; acc1.y += v1.y * w[p];
            acc1.z += v1.z * w[p]; acc1.w += v1.w * w[p];
        }
        *(float4*)&out[orow + c4] =
            make_float4(acc0.x * invL, acc0.y * invL, acc0.z * invL, acc0.w * invL);
        *(float4*)&out[orow + c4 + 4] =
            make_float4(acc1.x * invL, acc1.y * invL, acc1.z * invL, acc1.w * invL);
    }
}

// ---------------------------------------------------------------------------
extern "C" void kernel_launch(void* const* d_in, const int* in_sizes, int n_in,
                              void* d_out, int out_size)
{
    const float* x  = (const float*)d_in[0];
    const float* Wq = (const float*)d_in[1];
    const float* Wk = (const float*)d_in[2];
    const float* Wv = (const float*)d_in[3];
    float* out = (float*)d_out;

    cudaFuncSetAttribute(proj_mma_kernel,
                         cudaFuncAttributeMaxDynamicSharedMemorySize, PROJ_SMEM);
    cudaFuncSetAttribute(attn_mma_kernel,
                         cudaFuncAttributeMaxDynamicSharedMemorySize, ATTN_SMEM);

    const int prep_threads = NCHUNK_ * 8 * NTOT_ * 4;
    prep_w_kernel<<<(prep_threads + 255) / 256, 256>>>(Wq, Wk, Wv);
    proj_mma_kernel<<<M_ / 64, 256, PROJ_SMEM>>>(x);
    attn_mma_kernel<<<NGROUPS_, 128, ATTN_SMEM>>>(out);
}

// round 12
// speedup vs baseline: 1.0680x; 1.0680x over previous
#include <cuda_runtime.h>
#include <cuda_fp16.h>
#include <cstdint>

// Problem constants
static constexpr int B_  = 8;
static constexpr int T_  = 2048;
static constexpr int D_  = 1024;
static constexpr int HD_ = 64;
static constexpr int M_  = B_ * T_;       // 16384 rows
static constexpr int NTOT_ = 192;         // q|k|v fused output columns
static constexpr int TK_ = 64;            // K per chunk (128B fp16 rows)
static constexpr int NCHUNK_ = D_ / TK_;  // 16

// Attention split-work constants: chunks of <=9 kt-tiles.
static constexpr int CHUNK_ = 9;
static constexpr int GPB_ = 74;           // groups per batch: sum ceil((qt+1)/9)
static constexpr int NGROUPS_ = GPB_ * B_; // 592

// Device-global scratch (fp16 hi-only; q pre-scaled by 0.125*log2e).
__device__ __align__(16) __half g_qhi[(size_t)M_ * HD_];
__device__ __align__(16) __half g_khi[(size_t)M_ * HD_];
__device__ __align__(16) __half g_vhi[(size_t)M_ * HD_];
// Pre-transposed + swizzled fp16 W-hi tiles: [chunk][n=0..191][k=0..63]
static constexpr size_t WTILE_BYTES = (size_t)NTOT_ * 128;   // 24576 per chunk
__device__ __align__(16) uint8_t g_bhi[(size_t)NCHUNK_ * WTILE_BYTES];
// Attention partials: per group O[64][64] fp32 + per row (m, l)
__device__ __align__(16) float g_pO[(size_t)NGROUPS_ * 64 * 64];
__device__ __align__(16) float g_pML[(size_t)NGROUPS_ * 64 * 2];

__host__ __device__ __forceinline__ uint32_t swz128(uint32_t off) {
    return off ^ ((off >> 3) & 0x70);
}
__device__ __forceinline__ uint32_t smem_u32(const void* p) {
    uint32_t a;
    asm("{ .reg .u64 t; cvta.to.shared.u64 t, %1; cvt.u32.u64 %0, t; }"
        : "=r"(a) : "l"(p));
    return a;
}
__device__ __forceinline__ void ldsm_x4(uint32_t (&r)[4], uint32_t addr) {
    asm volatile("ldmatrix.sync.aligned.m8n8.x4.shared.b16 {%0,%1,%2,%3}, [%4];"
                 : "=r"(r[0]), "=r"(r[1]), "=r"(r[2]), "=r"(r[3]) : "r"(addr));
}
__device__ __forceinline__ void ldsm_x2(uint32_t (&r)[2], uint32_t addr) {
    asm volatile("ldmatrix.sync.aligned.m8n8.x2.shared.b16 {%0,%1}, [%2];"
                 : "=r"(r[0]), "=r"(r[1]) : "r"(addr));
}
__device__ __forceinline__ void ldsm_x4_trans(uint32_t (&r)[4], uint32_t addr) {
    asm volatile("ldmatrix.sync.aligned.m8n8.x4.trans.shared.b16 {%0,%1,%2,%3}, [%4];"
                 : "=r"(r[0]), "=r"(r[1]), "=r"(r[2]), "=r"(r[3]) : "r"(addr));
}
__device__ __forceinline__ void mma_f16(float (&d)[4], const uint32_t (&a)[4],
                                        uint32_t b0, uint32_t b1) {
    asm volatile(
        "mma.sync.aligned.m16n8k16.row.col.f32.f16.f16.f32 "
        "{%0,%1,%2,%3}, {%4,%5,%6,%7}, {%8,%9}, {%0,%1,%2,%3};"
        : "+f"(d[0]), "+f"(d[1]), "+f"(d[2]), "+f"(d[3])
        : "r"(a[0]), "r"(a[1]), "r"(a[2]), "r"(a[3]), "r"(b0), "r"(b1));
}
__device__ __forceinline__ uint32_t pack_h2(float lo, float hi) {
    __half l = __float2half_rn(lo);
    __half h = __float2half_rn(hi);
    return ((uint32_t)__half_as_ushort(h) << 16) | __half_as_ushort(l);
}
__device__ __forceinline__ uint32_t f2h2(float lo, float hi) {
    uint32_t r;
    asm("cvt.rn.f16x2.f32 %0, %1, %2;" : "=r"(r) : "f"(hi), "f"(lo));
    return r;
}
__device__ __forceinline__ uint32_t ex2h2(uint32_t x) {
    uint32_t r;
    asm("ex2.approx.f16x2 %0, %1;" : "=r"(r) : "r"(x));
    return r;
}
__device__ __forceinline__ float2 h22f2(uint32_t w) {
    __half2 h;
    *(uint32_t*)&h = w;
    return __half22float2(h);
}
__device__ __forceinline__ float ex2f(float x) {
    float y;
    asm("ex2.approx.ftz.f32 %0, %1;" : "=f"(y) : "f"(x));
    return y;
}
__device__ __forceinline__ void cp_async16(uint32_t dst, const void* src) {
    asm volatile("cp.async.ca.shared.global [%0], [%1], 16;"
                 :: "r"(dst), "l"(src));
}
#define CP_COMMIT() asm volatile("cp.async.commit_group;" ::: "memory")
#define CP_WAIT0()  asm volatile("cp.async.wait_group 0;" ::: "memory")
#define CP_WAIT1()  asm volatile("cp.async.wait_group 1;" ::: "memory")

static constexpr float SCALE_Q = 0.125f * 1.4426950408889634f;  // 1/sqrt(64)*log2e

// ---------------------------------------------------------------------------
// Kernel 0: W -> fp16 hi, transposed to [n][k] rows, SW128 swizzled.
// ---------------------------------------------------------------------------
__global__ void prep_w_kernel(const float* __restrict__ Wq,
                              const float* __restrict__ Wk,
                              const float* __restrict__ Wv)
{
    const int th = blockIdx.x * blockDim.x + threadIdx.x;
    if (th >= NCHUNK_ * 8 * NTOT_ * 4) return;
    const int jh = th & 3;
    const int t = th >> 2;
    const int c = t % NTOT_;
    const int rest = t / NTOT_;
    const int kg = rest % 8;
    const int chunk = rest / 8;
    const int n = c & 63;
    const float* W = (c < 64) ? Wq : (c < 128) ? Wk : Wv;
    const int k0 = chunk * TK_ + kg * 8 + jh * 2;

    const float a = W[(size_t)k0 * HD_ + n];
    const float b = W[(size_t)(k0 + 1) * HD_ + n];
    const size_t base = (size_t)chunk * WTILE_BYTES;
    const uint32_t off = swz128((uint32_t)c * 128u + (uint32_t)kg * 16u) + jh * 4u;
    *(uint32_t*)(g_bhi + base + off) = pack_h2(a, b);
}

// ---------------------------------------------------------------------------
// Kernel 1: QKV projection, mma.sync fp16 1-term. x staged as RAW fp32 via
// cp.async; smem->smem convert after pipelined wait (no exposed LDG latency).
// Stage: [A32 16K][Ah 8K][B 24K] = 48K x 2 stages. 2 CTAs/SM.
// ---------------------------------------------------------------------------
static constexpr int A32_TILE = 64 * 64 * 4;       // 16384 bytes (fp32)
static constexpr int AH_TILE  = 64 * 128;          // 8192 bytes (fp16)
static constexpr int B_TILE   = NTOT_ * 128;       // 24576 bytes
static constexpr int PROJ_STAGE = A32_TILE + AH_TILE + B_TILE;   // 49152
static constexpr int PROJ_SMEM  = 1024 + 2 * PROJ_STAGE;         // 99328

__global__ __launch_bounds__(256, 2) void proj_mma_kernel(const float* __restrict__ x)
{
    extern __shared__ uint8_t dynsm[];
    const uint32_t raw = smem_u32(dynsm);
    const uint32_t base = (raw + 1023u) & ~1023u;
    uint8_t* const sm = dynsm + (base - raw);

    const int tid = threadIdx.x;
    const int wid = tid >> 5;
    const int lane = tid & 31;
    const size_t row0g = (size_t)blockIdx.x * 64;

    float C[4][3][4];
#pragma unroll
    for (int mt = 0; mt < 4; mt++)
#pragma unroll
        for (int nt = 0; nt < 3; nt++)
#pragma unroll
            for (int e = 0; e < 4; e++) C[mt][nt][e] = 0.0f;

    const uint32_t a_row = (uint32_t)(lane & 15);
    const uint32_t a_kb  = (uint32_t)((lane >> 4) * 16);
    const uint32_t b_row = (uint32_t)(lane & 7);
    const uint32_t b_kb  = (uint32_t)(((lane >> 3) & 1) * 16);

    // Issue cp.async for chunk kc into stage st: raw fp32 x + pre-swizzled B.
    auto issue = [&](int st, int kc) {
        const uint32_t sb = base + st * PROJ_STAGE;
        // A32: 1024 x 16B
#pragma unroll
        for (int i = 0; i < 4; i++) {
            const int idx = tid + i * 256;     // 0..1023
            const int row = idx >> 4;
            const int c4  = idx & 15;
            cp_async16(sb + idx * 16, &x[(row0g + row) * D_ + kc * TK_ + c4 * 4]);
        }
        // B: 1536 x 16B
        const uint8_t* srcH = g_bhi + (size_t)kc * WTILE_BYTES;
#pragma unroll
        for (int i = 0; i < 6; i++) {
            const int idx = tid + i * 256;
            cp_async16(sb + A32_TILE + AH_TILE + idx * 16, srcH + idx * 16);
        }
    };

    issue(0, 0);
    CP_COMMIT();

    for (int kc = 0; kc < NCHUNK_; kc++) {
        const int st = kc & 1;
        if (kc + 1 < NCHUNK_) {
            issue(st ^ 1, kc + 1);
            CP_COMMIT();
            CP_WAIT1();
        } else {
            CP_WAIT0();
        }
        __syncthreads();

        const uint32_t sb = base + st * PROJ_STAGE;
        // Convert fp32 stage -> fp16 swizzled tile (smem -> smem)
        {
            const float* a32 = (const float*)(sm + st * PROJ_STAGE);
            uint8_t* ah = sm + st * PROJ_STAGE + A32_TILE;
#pragma unroll
            for (int i = 0; i < 4; i++) {
                const int idx = tid + i * 256;
                const int row = idx >> 4;
                const int c4  = idx & 15;
                const float4 v = *(const float4*)&a32[row * 64 + c4 * 4];
                const uint32_t h0 = pack_h2(v.x, v.y);
                const uint32_t h1 = pack_h2(v.z, v.w);
                const uint32_t off = swz128((uint32_t)row * 128u + (uint32_t)c4 * 8u);
                *(uint2*)(ah + off) = make_uint2(h0, h1);
            }
        }
        __syncthreads();

        const uint32_t sAh = sb + A32_TILE;
        const uint32_t sBh = sb + A32_TILE + AH_TILE;

#pragma unroll
        for (int ks = 0; ks < 4; ks++) {
            uint32_t Ah[4][4];
#pragma unroll
            for (int mt = 0; mt < 4; mt++) {
                const uint32_t roff =
                    swz128((uint32_t)(mt * 16 + a_row) * 128u +
                           (uint32_t)ks * 32u + a_kb);
                ldsm_x4(Ah[mt], sAh + roff);
            }
#pragma unroll
            for (int nt = 0; nt < 3; nt++) {
                const uint32_t boff =
                    swz128((uint32_t)(wid * 24 + nt * 8 + b_row) * 128u +
                           (uint32_t)ks * 32u + b_kb);
                uint32_t Bh[2];
                ldsm_x2(Bh, sBh + boff);
#pragma unroll
                for (int mt = 0; mt < 4; mt++) {
                    mma_f16(C[mt][nt], Ah[mt], Bh[0], Bh[1]);
                }
            }
        }
        __syncthreads();
    }

    // Epilogue: qhi (x SCALE_Q), khi, vhi
#pragma unroll
    for (int mt = 0; mt < 4; mt++) {
        const size_t r = row0g + mt * 16 + (lane >> 2);
#pragma unroll
        for (int nt = 0; nt < 3; nt++) {
            const int c = wid * 24 + nt * 8 + 2 * (lane & 3);
            const int n = c & 63;
#pragma unroll
            for (int half = 0; half < 2; half++) {
                const size_t rr = r + half * 8;
                float v0 = C[mt][nt][half * 2 + 0];
                float v1 = C[mt][nt][half * 2 + 1];
                __half* o;
                if (c < 64) {
                    v0 *= SCALE_Q; v1 *= SCALE_Q;
                    o = g_qhi;
                } else {
                    o = (c < 128) ? g_khi : g_vhi;
                }
                *(uint32_t*)&o[rr * HD_ + n] = pack_h2(v0, v1);
            }
        }
    }
}

// ---------------------------------------------------------------------------
// Kernel 2: flash attention, flat chunk decomposition. s==1 qtiles store
// normalized output directly; s>1 groups write partials for the merge kernel.
// ---------------------------------------------------------------------------
static constexpr int Q_BYTES  = 64 * 128;           // 8192
static constexpr int KV_STAGE = 2 * 64 * 128;       // 16384 (khi|vhi)
static constexpr int ATTN_SMEM = 1024 + Q_BYTES + 2 * KV_STAGE;  // 41984

__global__ __launch_bounds__(128, 4) void attn_mma_kernel(float* __restrict__ out)
{
    extern __shared__ uint8_t dynsm[];
    const uint32_t raw = smem_u32(dynsm);
    const uint32_t base = (raw + 1023u) & ~1023u;

    const int tid = threadIdx.x;
    const int wi  = tid >> 5;
    const int lane = tid & 31;

    // ---- decode work item: batch, q-tile, kt chunk ----
    const int bid = blockIdx.x;
    const int b = bid / GPB_;
    int r = bid % GPB_;
    int qt = 31, s = 4;
    for (qt = 31; qt >= 0; qt--) {
        s = (qt + CHUNK_) / CHUNK_;
        if (r < s) break;
        r -= s;
    }
    const int n = qt + 1;
    const int cbase = n / s, crem = n % s;
    const int kt0 = r * cbase + (r < crem ? r : crem);
    const int niter = cbase + (r < crem ? 1 : 0);

    const uint32_t sQ  = base;
    const uint32_t sKV = base + Q_BYTES;
    const size_t qrow0 = (size_t)b * T_ + (size_t)qt * 64;

#pragma unroll
    for (int i = 0; i < 4; i++) {
        const int idx = tid + i * 128;
        const int row = idx >> 3;
        const int c16 = idx & 7;
        const uint32_t doff = swz128((uint32_t)row * 128u + (uint32_t)c16 * 16u);
        cp_async16(sQ + doff, &g_qhi[(qrow0 + row) * HD_ + c16 * 8]);
    }
    CP_COMMIT();

    auto prefetch_kv = [&](int kt, int stage) {
        const uint32_t sb = sKV + stage * KV_STAGE;
        const size_t krow0 = (size_t)b * T_ + (size_t)kt * 64;
#pragma unroll
        for (int i = 0; i < 8; i++) {
            const int idx = tid + i * 128;
            const int arr = idx >> 9;
            const int row = (idx >> 3) & 63;
            const int c16 = idx & 7;
            const uint32_t doff = swz128((uint32_t)row * 128u + (uint32_t)c16 * 16u);
            const __half* src = arr ? g_vhi : g_khi;
            cp_async16(sb + arr * 8192 + doff, &src[(krow0 + row) * HD_ + c16 * 8]);
        }
    };
    prefetch_kv(kt0, 0);
    CP_COMMIT();
    CP_WAIT0();
    __syncthreads();

    uint32_t Qh[4][4];
    {
        const uint32_t a_row = (uint32_t)(lane & 15);
        const uint32_t a_kb  = (uint32_t)((lane >> 4) * 16);
#pragma unroll
        for (int ks = 0; ks < 4; ks++) {
            const uint32_t roff =
                swz128((uint32_t)(wi * 16 + a_row) * 128u + (uint32_t)ks * 32u + a_kb);
            ldsm_x4(Qh[ks], sQ + roff);
        }
    }

    float O[8][4];
#pragma unroll
    for (int nh = 0; nh < 8; nh++)
#pragma unroll
        for (int e = 0; e < 4; e++) O[nh][e] = 0.0f;
    float m0 = -1e30f, m1 = -1e30f, l0 = 0.0f, l1 = 0.0f;

    const int kg  = lane >> 3;
    const uint32_t k_row8 = (uint32_t)(lane & 7);
    const uint32_t k_rowsel = (uint32_t)(kg >> 1) * 8;
    const uint32_t k_kb = (uint32_t)(kg & 1) * 16;
    const uint32_t v_rowsel = (uint32_t)(kg & 1) * 8;
    const uint32_t v_colsel = (uint32_t)(kg >> 1) * 16;
    const int q2 = 2 * (lane & 3);
    const int rloc = (lane >> 2);

    for (int i = 0; i < niter; i++) {
        if (i + 1 < niter) prefetch_kv(kt0 + i + 1, (i + 1) & 1);
        CP_COMMIT();

        const int kt = kt0 + i;
        const uint32_t sb = sKV + (i & 1) * KV_STAGE;
        const uint32_t sKh = sb;
        const uint32_t sVh = sb + 8192;

        float S[8][4];
#pragma unroll
        for (int nt = 0; nt < 8; nt++)
#pragma unroll
            for (int e = 0; e < 4; e++) S[nt][e] = 0.0f;

#pragma unroll
        for (int ks = 0; ks < 4; ks++) {
#pragma unroll
            for (int ntp = 0; ntp < 4; ntp++) {
                const uint32_t boff =
                    swz128((uint32_t)(ntp * 16 + k_rowsel + k_row8) * 128u +
                           (uint32_t)ks * 32u + k_kb);
                uint32_t Kf[4];
                ldsm_x4(Kf, sKh + boff);
                mma_f16(S[2 * ntp],     Qh[ks], Kf[0], Kf[1]);
                mma_f16(S[2 * ntp + 1], Qh[ks], Kf[2], Kf[3]);
            }
        }

        if (kt == qt) {
            const int r0 = wi * 16 + rloc;
#pragma unroll
            for (int nt = 0; nt < 8; nt++) {
                const int c0 = nt * 8 + q2;
                if (c0 > r0)     S[nt][0] = -1e30f;
                if (c0 + 1 > r0) S[nt][1] = -1e30f;
                if (c0 > r0 + 8)     S[nt][2] = -1e30f;
                if (c0 + 1 > r0 + 8) S[nt][3] = -1e30f;
            }
        }

        float mx0 = -1e30f, mx1 = -1e30f;
#pragma unroll
        for (int nt = 0; nt < 8; nt++) {
            mx0 = fmaxf(mx0, fmaxf(S[nt][0], S[nt][1]));
            mx1 = fmaxf(mx1, fmaxf(S[nt][2], S[nt][3]));
        }
        mx0 = fmaxf(mx0, __shfl_xor_sync(0xffffffffu, mx0, 1));
        mx0 = fmaxf(mx0, __shfl_xor_sync(0xffffffffu, mx0, 2));
        mx1 = fmaxf(mx1, __shfl_xor_sync(0xffffffffu, mx1, 1));
        mx1 = fmaxf(mx1, __shfl_xor_sync(0xffffffffu, mx1, 2));
        const float mn0 = fmaxf(m0, mx0);
        const float mn1 = fmaxf(m1, mx1);
        const float a0 = ex2f(m0 - mn0);
        const float a1 = ex2f(m1 - mn1);
        m0 = mn0; m1 = mn1;

        uint32_t P[4][4];
        float sum0 = 0.0f, sum1 = 0.0f;
#pragma unroll
        for (int nt = 0; nt < 8; nt++) {
            const uint32_t w01 = ex2h2(f2h2(S[nt][0] - mn0, S[nt][1] - mn0));
            const uint32_t w23 = ex2h2(f2h2(S[nt][2] - mn1, S[nt][3] - mn1));
            P[nt >> 1][(nt & 1) * 2 + 0] = w01;
            P[nt >> 1][(nt & 1) * 2 + 1] = w23;
            const float2 f01 = h22f2(w01);
            const float2 f23 = h22f2(w23);
            sum0 += f01.x + f01.y;
            sum1 += f23.x + f23.y;
        }
        sum0 += __shfl_xor_sync(0xffffffffu, sum0, 1);
        sum0 += __shfl_xor_sync(0xffffffffu, sum0, 2);
        sum1 += __shfl_xor_sync(0xffffffffu, sum1, 1);
        sum1 += __shfl_xor_sync(0xffffffffu, sum1, 2);
        l0 = l0 * a0 + sum0;
        l1 = l1 * a1 + sum1;

#pragma unroll
        for (int nh = 0; nh < 8; nh++) {
            O[nh][0] *= a0; O[nh][1] *= a0;
            O[nh][2] *= a1; O[nh][3] *= a1;
        }

#pragma unroll
        for (int t = 0; t < 4; t++) {
#pragma unroll
            for (int nhp = 0; nhp < 4; nhp++) {
                const uint32_t voff =
                    swz128((uint32_t)(t * 16 + v_rowsel + k_row8) * 128u +
                           (uint32_t)nhp * 32u + v_colsel);
                uint32_t Vf[4];
                ldsm_x4_trans(Vf, sVh + voff);
                mma_f16(O[2 * nhp],     P[t], Vf[0], Vf[1]);
                mma_f16(O[2 * nhp + 1], P[t], Vf[2], Vf[3]);
            }
        }

        CP_WAIT0();
        __syncthreads();
    }

    const int row0 = wi * 16 + rloc;

    if (s == 1) {
        // ---- single-chunk qtile: normalize and store directly ----
        const float il0 = 1.0f / l0;
        const float il1 = 1.0f / l1;
        const size_t grow = qrow0 + (size_t)row0;
#pragma unroll
        for (int nh = 0; nh < 8; nh++) {
            const int hcol = nh * 8 + q2;
            *(float2*)&out[grow * HD_ + hcol] =
                make_float2(O[nh][0] * il0, O[nh][1] * il0);
            *(float2*)&out[(grow + 8) * HD_ + hcol] =
                make_float2(O[nh][2] * il1, O[nh][3] * il1);
        }
        return;
    }

    // ---- write partials to gmem ----
    float* const pO = g_pO + (size_t)bid * 4096;
    if ((lane & 3) == 0) {
        float* const pml = g_pML + (size_t)bid * 128;
        *(float2*)&pml[row0 * 2]       = make_float2(m0, l0);
        *(float2*)&pml[(row0 + 8) * 2] = make_float2(m1, l1);
    }
#pragma unroll
    for (int nh = 0; nh < 8; nh++) {
        const int hcol = nh * 8 + q2;
        *(float2*)&pO[row0 * 64 + hcol]       = make_float2(O[nh][0], O[nh][1]);
        *(float2*)&pO[(row0 + 8) * 64 + hcol] = make_float2(O[nh][2], O[nh][3]);
    }
}

// ---------------------------------------------------------------------------
// Kernel 3: merge partials for split qtiles only (qt >= 9).
// One thread per 8 output floats: 94208 threads, grid 368 x 256.
// ---------------------------------------------------------------------------
__global__ __launch_bounds__(256) void attn_merge_kernel(float* __restrict__ out)
{
    const int gid = blockIdx.x * 256 + threadIdx.x;    // 0..94207
    if (gid >= 8 * 23 * 64 * 8) return;
    const int row_glob = gid >> 3;                     // 0..11775
    const int seg = (gid & 7) * 8;

    const int b = row_glob / 1472;                     // 23*64 = 1472
    const int within = row_glob % 1472;
    const int qt  = 9 + (within >> 6);                 // 9..31
    const int row = within & 63;

    int off = 0;
    for (int q = qt + 1; q < 32; q++) off += (q + CHUNK_) / CHUNK_;
    const int s = (qt + CHUNK_) / CHUNK_;
    const int g0 = b * GPB_ + off;

    float mp[4], lp[4];
    float M = -1e30f;
#pragma unroll 4
    for (int p = 0; p < s; p++) {
        const float2 ml = *(const float2*)&g_pML[(size_t)(g0 + p) * 128 + row * 2];
        mp[p] = ml.x; lp[p] = ml.y;
        M = fmaxf(M, ml.x);
    }
    float w[4];
    float L = 0.0f;
#pragma unroll 4
    for (int p = 0; p < s; p++) {
        w[p] = ex2f(mp[p] - M);
        L += lp[p] * w[p];
    }
    const float invL = 1.0f / L;

    float4 acc0 = make_float4(0.f, 0.f, 0.f, 0.f);
    float4 acc1 = make_float4(0.f, 0.f, 0.f, 0.f);
#pragma unroll 4
    for (int p = 0; p < s; p++) {
        const float* src = &g_pO[(size_t)(g0 + p) * 4096 + row * 64 + seg];
        const float4 v0 = *(const float4*)&src[0];
        const float4 v1 = *(const float4*)&src[4];
        acc0.x += v0.x * w[p]; acc0.y += v0.y * w[p];
        acc0.z += v0.z * w[p]; acc0.w += v0.w * w[p];
        acc1.x += v1.x * w[p]; acc1.y += v1.y * w[p];
        acc1.z += v1.z * w[p]; acc1.w += v1.w * w[p];
    }

    const size_t orow = ((size_t)b * T_ + (size_t)qt * 64 + row) * HD_ + seg;
    *(float4*)&out[orow] =
        make_float4(acc0.x * invL, acc0.y * invL, acc0.z * invL, acc0.w * invL);
    *(float4*)&out[orow + 4] =
        make_float4(acc1.x * invL, acc1.y * invL, acc1.z * invL, acc1.w * invL);
}

// ---------------------------------------------------------------------------
extern "C" void kernel_launch(void* const* d_in, const int* in_sizes, int n_in,
                              void* d_out, int out_size)
{
    const float* x  = (const float*)d_in[0];
    const float* Wq = (const float*)d_in[1];
    const float* Wk = (const float*)d_in[2];
    const float* Wv = (const float*)d_in[3];
    float* out = (float*)d_out;

    cudaFuncSetAttribute(proj_mma_kernel,
                         cudaFuncAttributeMaxDynamicSharedMemorySize, PROJ_SMEM);
    cudaFuncSetAttribute(attn_mma_kernel,
                         cudaFuncAttributeMaxDynamicSharedMemorySize, ATTN_SMEM);

    const int prep_threads = NCHUNK_ * 8 * NTOT_ * 4;
    prep_w_kernel<<<(prep_threads + 255) / 256, 256>>>(Wq, Wk, Wv);
    proj_mma_kernel<<<M_ / 64, 256, PROJ_SMEM>>>(x);
    attn_mma_kernel<<<NGROUPS_, 128, ATTN_SMEM>>>(out);
    attn_merge_kernel<<<368, 256>>>(out);
}

// round 13
// speedup vs baseline: 1.1302x; 1.0582x over previous
#include <cuda_runtime.h>
#include <cuda_fp16.h>
#include <cstdint>

// Problem constants
static constexpr int B_  = 8;
static constexpr int T_  = 2048;
static constexpr int D_  = 1024;
static constexpr int HD_ = 64;
static constexpr int M_  = B_ * T_;       // 16384 rows
static constexpr int NTOT_ = 192;         // q|k|v fused output columns
static constexpr int TK_ = 64;            // K per chunk (128B fp16 rows)
static constexpr int NCHUNK_ = D_ / TK_;  // 16

// Device-global scratch (fp16 hi-only; q pre-scaled by 0.125*log2e).
__device__ __align__(16) __half g_qhi[(size_t)M_ * HD_];
__device__ __align__(16) __half g_khi[(size_t)M_ * HD_];
__device__ __align__(16) __half g_vhi[(size_t)M_ * HD_];
// Pre-transposed + swizzled fp16 W-hi tiles: [chunk][n=0..191][k=0..63]
static constexpr size_t WTILE_BYTES = (size_t)NTOT_ * 128;   // 24576 per chunk
__device__ __align__(16) uint8_t g_bhi[(size_t)NCHUNK_ * WTILE_BYTES];

__host__ __device__ __forceinline__ uint32_t swz128(uint32_t off) {
    return off ^ ((off >> 3) & 0x70);
}
__device__ __forceinline__ uint32_t smem_u32(const void* p) {
    uint32_t a;
    asm("{ .reg .u64 t; cvta.to.shared.u64 t, %1; cvt.u32.u64 %0, t; }"
        : "=r"(a) : "l"(p));
    return a;
}
__device__ __forceinline__ void ldsm_x4(uint32_t (&r)[4], uint32_t addr) {
    asm volatile("ldmatrix.sync.aligned.m8n8.x4.shared.b16 {%0,%1,%2,%3}, [%4];"
                 : "=r"(r[0]), "=r"(r[1]), "=r"(r[2]), "=r"(r[3]) : "r"(addr));
}
__device__ __forceinline__ void ldsm_x2(uint32_t (&r)[2], uint32_t addr) {
    asm volatile("ldmatrix.sync.aligned.m8n8.x2.shared.b16 {%0,%1}, [%2];"
                 : "=r"(r[0]), "=r"(r[1]) : "r"(addr));
}
__device__ __forceinline__ void ldsm_x4_trans(uint32_t (&r)[4], uint32_t addr) {
    asm volatile("ldmatrix.sync.aligned.m8n8.x4.trans.shared.b16 {%0,%1,%2,%3}, [%4];"
                 : "=r"(r[0]), "=r"(r[1]), "=r"(r[2]), "=r"(r[3]) : "r"(addr));
}
__device__ __forceinline__ void mma_f16(float (&d)[4], const uint32_t (&a)[4],
                                        uint32_t b0, uint32_t b1) {
    asm volatile(
        "mma.sync.aligned.m16n8k16.row.col.f32.f16.f16.f32 "
        "{%0,%1,%2,%3}, {%4,%5,%6,%7}, {%8,%9}, {%0,%1,%2,%3};"
        : "+f"(d[0]), "+f"(d[1]), "+f"(d[2]), "+f"(d[3])
        : "r"(a[0]), "r"(a[1]), "r"(a[2]), "r"(a[3]), "r"(b0), "r"(b1));
}
__device__ __forceinline__ uint32_t pack_h2(float lo, float hi) {
    __half l = __float2half_rn(lo);
    __half h = __float2half_rn(hi);
    return ((uint32_t)__half_as_ushort(h) << 16) | __half_as_ushort(l);
}
__device__ __forceinline__ uint32_t f2h2(float lo, float hi) {
    uint32_t r;
    asm("cvt.rn.f16x2.f32 %0, %1, %2;" : "=r"(r) : "f"(hi), "f"(lo));
    return r;
}
__device__ __forceinline__ uint32_t ex2h2(uint32_t x) {
    uint32_t r;
    asm("ex2.approx.f16x2 %0, %1;" : "=r"(r) : "r"(x));
    return r;
}
__device__ __forceinline__ float2 h22f2(uint32_t w) {
    __half2 h;
    *(uint32_t*)&h = w;
    return __half22float2(h);
}
__device__ __forceinline__ float ex2f(float x) {
    float y;
    asm("ex2.approx.ftz.f32 %0, %1;" : "=f"(y) : "f"(x));
    return y;
}
__device__ __forceinline__ void cp_async16(uint32_t dst, const void* src) {
    asm volatile("cp.async.ca.shared.global [%0], [%1], 16;"
                 :: "r"(dst), "l"(src));
}
#define CP_COMMIT() asm volatile("cp.async.commit_group;" ::: "memory")
#define CP_WAIT0()  asm volatile("cp.async.wait_group 0;" ::: "memory")
#define CP_WAIT1()  asm volatile("cp.async.wait_group 1;" ::: "memory")
#define GROUP_BAR(id) asm volatile("bar.sync %0, 128;" :: "r"(id) : "memory")

static constexpr float SCALE_Q = 0.125f * 1.4426950408889634f;  // 1/sqrt(64)*log2e

// ---------------------------------------------------------------------------
// Kernel 0: W -> fp16 hi, transposed to [n][k] rows, SW128 swizzled.
// ---------------------------------------------------------------------------
__global__ void prep_w_kernel(const float* __restrict__ Wq,
                              const float* __restrict__ Wk,
                              const float* __restrict__ Wv)
{
    const int th = blockIdx.x * blockDim.x + threadIdx.x;
    if (th >= NCHUNK_ * 8 * NTOT_ * 4) return;
    const int jh = th & 3;
    const int t = th >> 2;
    const int c = t % NTOT_;
    const int rest = t / NTOT_;
    const int kg = rest % 8;
    const int chunk = rest / 8;
    const int n = c & 63;
    const float* W = (c < 64) ? Wq : (c < 128) ? Wk : Wv;
    const int k0 = chunk * TK_ + kg * 8 + jh * 2;

    const float a = W[(size_t)k0 * HD_ + n];
    const float b = W[(size_t)(k0 + 1) * HD_ + n];
    const size_t base = (size_t)chunk * WTILE_BYTES;
    const uint32_t off = swz128((uint32_t)c * 128u + (uint32_t)kg * 16u) + jh * 4u;
    *(uint32_t*)(g_bhi + base + off) = pack_h2(a, b);
}

// ---------------------------------------------------------------------------
// Kernel 1: QKV projection, mma.sync fp16 1-term, cp.async staged fp32 A.
// (unchanged from R12)
// ---------------------------------------------------------------------------
static constexpr int A32_TILE = 64 * 64 * 4;       // 16384 bytes (fp32)
static constexpr int AH_TILE  = 64 * 128;          // 8192 bytes (fp16)
static constexpr int B_TILE   = NTOT_ * 128;       // 24576 bytes
static constexpr int PROJ_STAGE = A32_TILE + AH_TILE + B_TILE;   // 49152
static constexpr int PROJ_SMEM  = 1024 + 2 * PROJ_STAGE;         // 99328

__global__ __launch_bounds__(256, 2) void proj_mma_kernel(const float* __restrict__ x)
{
    extern __shared__ uint8_t dynsm[];
    const uint32_t raw = smem_u32(dynsm);
    const uint32_t base = (raw + 1023u) & ~1023u;
    uint8_t* const sm = dynsm + (base - raw);

    const int tid = threadIdx.x;
    const int wid = tid >> 5;
    const int lane = tid & 31;
    const size_t row0g = (size_t)blockIdx.x * 64;

    float C[4][3][4];
#pragma unroll
    for (int mt = 0; mt < 4; mt++)
#pragma unroll
        for (int nt = 0; nt < 3; nt++)
#pragma unroll
            for (int e = 0; e < 4; e++) C[mt][nt][e] = 0.0f;

    const uint32_t a_row = (uint32_t)(lane & 15);
    const uint32_t a_kb  = (uint32_t)((lane >> 4) * 16);
    const uint32_t b_row = (uint32_t)(lane & 7);
    const uint32_t b_kb  = (uint32_t)(((lane >> 3) & 1) * 16);

    auto issue = [&](int st, int kc) {
        const uint32_t sb = base + st * PROJ_STAGE;
#pragma unroll
        for (int i = 0; i < 4; i++) {
            const int idx = tid + i * 256;
            const int row = idx >> 4;
            const int c4  = idx & 15;
            cp_async16(sb + idx * 16, &x[(row0g + row) * D_ + kc * TK_ + c4 * 4]);
        }
        const uint8_t* srcH = g_bhi + (size_t)kc * WTILE_BYTES;
#pragma unroll
        for (int i = 0; i < 6; i++) {
            const int idx = tid + i * 256;
            cp_async16(sb + A32_TILE + AH_TILE + idx * 16, srcH + idx * 16);
        }
    };

    issue(0, 0);
    CP_COMMIT();

    for (int kc = 0; kc < NCHUNK_; kc++) {
        const int st = kc & 1;
        if (kc + 1 < NCHUNK_) {
            issue(st ^ 1, kc + 1);
            CP_COMMIT();
            CP_WAIT1();
        } else {
            CP_WAIT0();
        }
        __syncthreads();

        const uint32_t sb = base + st * PROJ_STAGE;
        {
            const float* a32 = (const float*)(sm + st * PROJ_STAGE);
            uint8_t* ah = sm + st * PROJ_STAGE + A32_TILE;
#pragma unroll
            for (int i = 0; i < 4; i++) {
                const int idx = tid + i * 256;
                const int row = idx >> 4;
                const int c4  = idx & 15;
                const float4 v = *(const float4*)&a32[row * 64 + c4 * 4];
                const uint32_t h0 = pack_h2(v.x, v.y);
                const uint32_t h1 = pack_h2(v.z, v.w);
                const uint32_t off = swz128((uint32_t)row * 128u + (uint32_t)c4 * 8u);
                *(uint2*)(ah + off) = make_uint2(h0, h1);
            }
        }
        __syncthreads();

        const uint32_t sAh = sb + A32_TILE;
        const uint32_t sBh = sb + A32_TILE + AH_TILE;

#pragma unroll
        for (int ks = 0; ks < 4; ks++) {
            uint32_t Ah[4][4];
#pragma unroll
            for (int mt = 0; mt < 4; mt++) {
                const uint32_t roff =
                    swz128((uint32_t)(mt * 16 + a_row) * 128u +
                           (uint32_t)ks * 32u + a_kb);
                ldsm_x4(Ah[mt], sAh + roff);
            }
#pragma unroll
            for (int nt = 0; nt < 3; nt++) {
                const uint32_t boff =
                    swz128((uint32_t)(wid * 24 + nt * 8 + b_row) * 128u +
                           (uint32_t)ks * 32u + b_kb);
                uint32_t Bh[2];
                ldsm_x2(Bh, sBh + boff);
#pragma unroll
                for (int mt = 0; mt < 4; mt++) {
                    mma_f16(C[mt][nt], Ah[mt], Bh[0], Bh[1]);
                }
            }
        }
        __syncthreads();
    }

    // Epilogue: qhi (x SCALE_Q), khi, vhi
#pragma unroll
    for (int mt = 0; mt < 4; mt++) {
        const size_t r = row0g + mt * 16 + (lane >> 2);
#pragma unroll
        for (int nt = 0; nt < 3; nt++) {
            const int c = wid * 24 + nt * 8 + 2 * (lane & 3);
            const int n = c & 63;
#pragma unroll
            for (int half = 0; half < 2; half++) {
                const size_t rr = r + half * 8;
                float v0 = C[mt][nt][half * 2 + 0];
                float v1 = C[mt][nt][half * 2 + 1];
                __half* o;
                if (c < 64) {
                    v0 *= SCALE_Q; v1 *= SCALE_Q;
                    o = g_qhi;
                } else {
                    o = (c < 128) ? g_khi : g_vhi;
                }
                *(uint32_t*)&o[rr * HD_ + n] = pack_h2(v0, v1);
            }
        }
    }
}

// ---------------------------------------------------------------------------
// Kernel 2: flash attention, 512-thr CTA = 4 groups of 128; group g handles
// kt-chunk g of ceil((qt+1)/4) tiles; in-CTA smem merge (conflict-free pad).
// One CTA per (b, qt), qt descending (LPT). 1 CTA/SM.
// ---------------------------------------------------------------------------
static constexpr int Q_BYTES   = 64 * 128;          // 8192
static constexpr int KV_STAGE  = 2 * 64 * 128;      // 16384 (khi|vhi)
static constexpr int KV_REGION = 2 * KV_STAGE;      // 32768 per group
static constexpr int ATTN_SMEM = 1024 + Q_BYTES + 4 * KV_REGION;  // 140288

__global__ __launch_bounds__(512, 1) void attn_mma_kernel(float* __restrict__ out)
{
    extern __shared__ uint8_t dynsm[];
    const uint32_t raw = smem_u32(dynsm);
    const uint32_t base = (raw + 1023u) & ~1023u;
    uint8_t* const smp = dynsm + (base - raw);

    const int tid = threadIdx.x;
    const int wid = tid >> 5;
    const int lane = tid & 31;
    const int grp = wid >> 2;             // 0..3
    const int wi  = wid & 3;              // warp within group
    const int gt  = tid & 127;            // thread within group

    const int bid = blockIdx.x;
    const int qt = 31 - (bid >> 3);       // largest work first
    const int b  = bid & 7;

    const int n = qt + 1;
    const int base4 = n >> 2;
    const int rem = n & 3;
    const int kt0 = grp * base4 + (grp < rem ? grp : rem);
    const int niter = base4 + (grp < rem ? 1 : 0);

    const uint32_t sQ  = base;
    const uint32_t sKV = base + Q_BYTES + grp * KV_REGION;
    const size_t qrow0 = (size_t)b * T_ + (size_t)qt * 64;

    // ---- Q via cp.async: 512 threads x 16B ----
    {
        const int row = tid >> 3;
        const int c16 = tid & 7;
        const uint32_t doff = swz128((uint32_t)row * 128u + (uint32_t)c16 * 16u);
        cp_async16(sQ + doff, &g_qhi[(qrow0 + row) * HD_ + c16 * 8]);
    }
    CP_COMMIT();

    auto prefetch_kv = [&](int kt, int stage) {
        const uint32_t sb = sKV + stage * KV_STAGE;
        const size_t krow0 = (size_t)b * T_ + (size_t)kt * 64;
#pragma unroll
        for (int i = 0; i < 8; i++) {
            const int idx = gt + i * 128;      // 0..1023
            const int arr = idx >> 9;          // 0 khi, 1 vhi
            const int row = (idx >> 3) & 63;
            const int c16 = idx & 7;
            const uint32_t doff = swz128((uint32_t)row * 128u + (uint32_t)c16 * 16u);
            const __half* src = arr ? g_vhi : g_khi;
            cp_async16(sb + arr * 8192 + doff, &src[(krow0 + row) * HD_ + c16 * 8]);
        }
    };
    if (niter > 0) prefetch_kv(kt0, 0);
    CP_COMMIT();
    CP_WAIT0();
    __syncthreads();

    // ---- Q fragments (shared qtile; rows by wi) ----
    uint32_t Qh[4][4];
    {
        const uint32_t a_row = (uint32_t)(lane & 15);
        const uint32_t a_kb  = (uint32_t)((lane >> 4) * 16);
#pragma unroll
        for (int ks = 0; ks < 4; ks++) {
            const uint32_t roff =
                swz128((uint32_t)(wi * 16 + a_row) * 128u + (uint32_t)ks * 32u + a_kb);
            ldsm_x4(Qh[ks], sQ + roff);
        }
    }

    float O[8][4];
#pragma unroll
    for (int nh = 0; nh < 8; nh++)
#pragma unroll
        for (int e = 0; e < 4; e++) O[nh][e] = 0.0f;
    float m0 = -1e30f, m1 = -1e30f, l0 = 0.0f, l1 = 0.0f;

    const int kg  = lane >> 3;
    const uint32_t k_row8 = (uint32_t)(lane & 7);
    const uint32_t k_rowsel = (uint32_t)(kg >> 1) * 8;
    const uint32_t k_kb = (uint32_t)(kg & 1) * 16;
    const uint32_t v_rowsel = (uint32_t)(kg & 1) * 8;
    const uint32_t v_colsel = (uint32_t)(kg >> 1) * 16;
    const int q2 = 2 * (lane & 3);
    const int rloc = (lane >> 2);

    for (int i = 0; i < niter; i++) {
        if (i + 1 < niter) prefetch_kv(kt0 + i + 1, (i + 1) & 1);
        CP_COMMIT();

        const int kt = kt0 + i;
        const uint32_t sb = sKV + (i & 1) * KV_STAGE;
        const uint32_t sKh = sb;
        const uint32_t sVh = sb + 8192;

        // ---- S = Q @ K^T ----
        float S[8][4];
#pragma unroll
        for (int nt = 0; nt < 8; nt++)
#pragma unroll
            for (int e = 0; e < 4; e++) S[nt][e] = 0.0f;

#pragma unroll
        for (int ks = 0; ks < 4; ks++) {
#pragma unroll
            for (int ntp = 0; ntp < 4; ntp++) {
                const uint32_t boff =
                    swz128((uint32_t)(ntp * 16 + k_rowsel + k_row8) * 128u +
                           (uint32_t)ks * 32u + k_kb);
                uint32_t Kf[4];
                ldsm_x4(Kf, sKh + boff);
                mma_f16(S[2 * ntp],     Qh[ks], Kf[0], Kf[1]);
                mma_f16(S[2 * ntp + 1], Qh[ks], Kf[2], Kf[3]);
            }
        }

        // ---- causal mask on diagonal tile ----
        if (kt == qt) {
            const int r0 = wi * 16 + rloc;
#pragma unroll
            for (int nt = 0; nt < 8; nt++) {
                const int c0 = nt * 8 + q2;
                if (c0 > r0)     S[nt][0] = -1e30f;
                if (c0 + 1 > r0) S[nt][1] = -1e30f;
                if (c0 > r0 + 8)     S[nt][2] = -1e30f;
                if (c0 + 1 > r0 + 8) S[nt][3] = -1e30f;
            }
        }

        // ---- online softmax (base-2), P in fp16x2 ----
        float mx0 = -1e30f, mx1 = -1e30f;
#pragma unroll
        for (int nt = 0; nt < 8; nt++) {
            mx0 = fmaxf(mx0, fmaxf(S[nt][0], S[nt][1]));
            mx1 = fmaxf(mx1, fmaxf(S[nt][2], S[nt][3]));
        }
        mx0 = fmaxf(mx0, __shfl_xor_sync(0xffffffffu, mx0, 1));
        mx0 = fmaxf(mx0, __shfl_xor_sync(0xffffffffu, mx0, 2));
        mx1 = fmaxf(mx1, __shfl_xor_sync(0xffffffffu, mx1, 1));
        mx1 = fmaxf(mx1, __shfl_xor_sync(0xffffffffu, mx1, 2));
        const float mn0 = fmaxf(m0, mx0);
        const float mn1 = fmaxf(m1, mx1);
        const float a0 = ex2f(m0 - mn0);
        const float a1 = ex2f(m1 - mn1);
        m0 = mn0; m1 = mn1;

        uint32_t P[4][4];
        float sum0 = 0.0f, sum1 = 0.0f;
#pragma unroll
        for (int nt = 0; nt < 8; nt++) {
            const uint32_t w01 = ex2h2(f2h2(S[nt][0] - mn0, S[nt][1] - mn0));
            const uint32_t w23 = ex2h2(f2h2(S[nt][2] - mn1, S[nt][3] - mn1));
            P[nt >> 1][(nt & 1) * 2 + 0] = w01;
            P[nt >> 1][(nt & 1) * 2 + 1] = w23;
            const float2 f01 = h22f2(w01);
            const float2 f23 = h22f2(w23);
            sum0 += f01.x + f01.y;
            sum1 += f23.x + f23.y;
        }
        sum0 += __shfl_xor_sync(0xffffffffu, sum0, 1);
        sum0 += __shfl_xor_sync(0xffffffffu, sum0, 2);
        sum1 += __shfl_xor_sync(0xffffffffu, sum1, 1);
        sum1 += __shfl_xor_sync(0xffffffffu, sum1, 2);
        l0 = l0 * a0 + sum0;
        l1 = l1 * a1 + sum1;

#pragma unroll
        for (int nh = 0; nh < 8; nh++) {
            O[nh][0] *= a0; O[nh][1] *= a0;
            O[nh][2] *= a1; O[nh][3] *= a1;
        }

        // ---- O += P @ V ----
#pragma unroll
        for (int t = 0; t < 4; t++) {
#pragma unroll
            for (int nhp = 0; nhp < 4; nhp++) {
                const uint32_t voff =
                    swz128((uint32_t)(t * 16 + v_rowsel + k_row8) * 128u +
                           (uint32_t)nhp * 32u + v_colsel);
                uint32_t Vf[4];
                ldsm_x4_trans(Vf, sVh + voff);
                mma_f16(O[2 * nhp],     P[t], Vf[0], Vf[1]);
                mma_f16(O[2 * nhp + 1], P[t], Vf[2], Vf[3]);
            }
        }

        CP_WAIT0();
        GROUP_BAR(1 + grp);
    }

    // ---- in-CTA merge: groups 1-3 stash partials in their KV regions ----
    // slot stride 33 floats -> conflict-free. mO: 128*33*4 = 16896 B; mML after.
    if (grp != 0) {
        float* const mO  = (float*)(smp + Q_BYTES + grp * KV_REGION);
        float* const mML = (float*)(smp + Q_BYTES + grp * KV_REGION + 16896);
#pragma unroll
        for (int nh = 0; nh < 8; nh++)
#pragma unroll
            for (int e = 0; e < 4; e++) mO[gt * 33 + nh * 4 + e] = O[nh][e];
        mML[gt * 4 + 0] = m0;
        mML[gt * 4 + 1] = l0;
        mML[gt * 4 + 2] = m1;
        mML[gt * 4 + 3] = l1;
    }
    __syncthreads();

    if (grp == 0) {
        float pm0[3], pl0[3], pm1[3], pl1[3];
        float M0 = m0, M1 = m1;
#pragma unroll
        for (int g = 0; g < 3; g++) {
            const float* mML = (const float*)(smp + Q_BYTES + (g + 1) * KV_REGION + 16896);
            pm0[g] = mML[gt * 4 + 0];
            pl0[g] = mML[gt * 4 + 1];
            pm1[g] = mML[gt * 4 + 2];
            pl1[g] = mML[gt * 4 + 3];
            M0 = fmaxf(M0, pm0[g]);
            M1 = fmaxf(M1, pm1[g]);
        }
        const float a0 = ex2f(m0 - M0);
        const float a1 = ex2f(m1 - M1);
        float pa0[3], pa1[3];
        float L0 = l0 * a0, L1 = l1 * a1;
#pragma unroll
        for (int g = 0; g < 3; g++) {
            pa0[g] = ex2f(pm0[g] - M0);
            pa1[g] = ex2f(pm1[g] - M1);
            L0 += pl0[g] * pa0[g];
            L1 += pl1[g] * pa1[g];
        }
        const float il0 = 1.0f / L0;
        const float il1 = 1.0f / L1;

        const int row0 = wi * 16 + rloc;
        const size_t grow = qrow0 + (size_t)row0;
#pragma unroll
        for (int nh = 0; nh < 8; nh++) {
            const int hcol = nh * 8 + q2;
            float o0 = O[nh][0] * a0;
            float o1 = O[nh][1] * a0;
            float o2 = O[nh][2] * a1;
            float o3 = O[nh][3] * a1;
#pragma unroll
            for (int g = 0; g < 3; g++) {
                const float* mO = (const float*)(smp + Q_BYTES + (g + 1) * KV_REGION);
                o0 += mO[gt * 33 + nh * 4 + 0] * pa0[g];
                o1 += mO[gt * 33 + nh * 4 + 1] * pa0[g];
                o2 += mO[gt * 33 + nh * 4 + 2] * pa1[g];
                o3 += mO[gt * 33 + nh * 4 + 3] * pa1[g];
            }
            *(float2*)&out[grow * HD_ + hcol] = make_float2(o0 * il0, o1 * il0);
            *(float2*)&out[(grow + 8) * HD_ + hcol] = make_float2(o2 * il1, o3 * il1);
        }
    }
}

// ---------------------------------------------------------------------------
extern "C" void kernel_launch(void* const* d_in, const int* in_sizes, int n_in,
                              void* d_out, int out_size)
{
    const float* x  = (const float*)d_in[0];
    const float* Wq = (const float*)d_in[1];
    const float* Wk = (const float*)d_in[2];
    const float* Wv = (const float*)d_in[3];
    float* out = (float*)d_out;

    cudaFuncSetAttribute(proj_mma_kernel,
                         cudaFuncAttributeMaxDynamicSharedMemorySize, PROJ_SMEM);
    cudaFuncSetAttribute(attn_mma_kernel,
                         cudaFuncAttributeMaxDynamicSharedMemorySize, ATTN_SMEM);

    const int prep_threads = NCHUNK_ * 8 * NTOT_ * 4;
    prep_w_kernel<<<(prep_threads + 255) / 256, 256>>>(Wq, Wk, Wv);
    proj_mma_kernel<<<M_ / 64, 256, PROJ_SMEM>>>(x);
    attn_mma_kernel<<<256, 512, ATTN_SMEM>>>(out);
}

// round 14
// speedup vs baseline: 1.1616x; 1.0277x over previous
#include <cuda_runtime.h>
#include <cuda_fp16.h>
#include <cstdint>

// Problem constants
static constexpr int B_  = 8;
static constexpr int T_  = 2048;
static constexpr int D_  = 1024;
static constexpr int HD_ = 64;
static constexpr int M_  = B_ * T_;       // 16384 rows
static constexpr int NTOT_ = 192;         // q|k|v fused output columns
static constexpr int TK_ = 64;            // K per chunk (128B fp16 rows)
static constexpr int NCHUNK_ = D_ / TK_;  // 16

// Device-global scratch (fp16 hi-only; q pre-scaled by 0.125*log2e).
__device__ __align__(16) __half g_qhi[(size_t)M_ * HD_];
__device__ __align__(16) __half g_khi[(size_t)M_ * HD_];
__device__ __align__(16) __half g_vhi[(size_t)M_ * HD_];
// Pre-transposed + swizzled fp16 W-hi tiles: [chunk][n=0..191][k=0..63]
static constexpr size_t WTILE_BYTES = (size_t)NTOT_ * 128;   // 24576 per chunk
__device__ __align__(16) uint8_t g_bhi[(size_t)NCHUNK_ * WTILE_BYTES];

__host__ __device__ __forceinline__ uint32_t swz128(uint32_t off) {
    return off ^ ((off >> 3) & 0x70);
}
__device__ __forceinline__ uint32_t smem_u32(const void* p) {
    uint32_t a;
    asm("{ .reg .u64 t; cvta.to.shared.u64 t, %1; cvt.u32.u64 %0, t; }"
        : "=r"(a) : "l"(p));
    return a;
}
__device__ __forceinline__ void ldsm_x4(uint32_t (&r)[4], uint32_t addr) {
    asm volatile("ldmatrix.sync.aligned.m8n8.x4.shared.b16 {%0,%1,%2,%3}, [%4];"
                 : "=r"(r[0]), "=r"(r[1]), "=r"(r[2]), "=r"(r[3]) : "r"(addr));
}
__device__ __forceinline__ void ldsm_x2(uint32_t (&r)[2], uint32_t addr) {
    asm volatile("ldmatrix.sync.aligned.m8n8.x2.shared.b16 {%0,%1}, [%2];"
                 : "=r"(r[0]), "=r"(r[1]) : "r"(addr));
}
__device__ __forceinline__ void ldsm_x4_trans(uint32_t (&r)[4], uint32_t addr) {
    asm volatile("ldmatrix.sync.aligned.m8n8.x4.trans.shared.b16 {%0,%1,%2,%3}, [%4];"
                 : "=r"(r[0]), "=r"(r[1]), "=r"(r[2]), "=r"(r[3]) : "r"(addr));
}
__device__ __forceinline__ void mma_f16(float (&d)[4], const uint32_t (&a)[4],
                                        uint32_t b0, uint32_t b1) {
    asm volatile(
        "mma.sync.aligned.m16n8k16.row.col.f32.f16.f16.f32 "
        "{%0,%1,%2,%3}, {%4,%5,%6,%7}, {%8,%9}, {%0,%1,%2,%3};"
        : "+f"(d[0]), "+f"(d[1]), "+f"(d[2]), "+f"(d[3])
        : "r"(a[0]), "r"(a[1]), "r"(a[2]), "r"(a[3]), "r"(b0), "r"(b1));
}
__device__ __forceinline__ uint32_t pack_h2(float lo, float hi) {
    __half l = __float2half_rn(lo);
    __half h = __float2half_rn(hi);
    return ((uint32_t)__half_as_ushort(h) << 16) | __half_as_ushort(l);
}
__device__ __forceinline__ uint32_t f2h2(float lo, float hi) {
    uint32_t r;
    asm("cvt.rn.f16x2.f32 %0, %1, %2;" : "=r"(r) : "f"(hi), "f"(lo));
    return r;
}
__device__ __forceinline__ uint32_t ex2h2(uint32_t x) {
    uint32_t r;
    asm("ex2.approx.f16x2 %0, %1;" : "=r"(r) : "r"(x));
    return r;
}
__device__ __forceinline__ float2 h22f2(uint32_t w) {
    __half2 h;
    *(uint32_t*)&h = w;
    return __half22float2(h);
}
__device__ __forceinline__ float ex2f(float x) {
    float y;
    asm("ex2.approx.ftz.f32 %0, %1;" : "=f"(y) : "f"(x));
    return y;
}
__device__ __forceinline__ void cp_async16(uint32_t dst, const void* src) {
    asm volatile("cp.async.ca.shared.global [%0], [%1], 16;"
                 :: "r"(dst), "l"(src));
}
#define CP_COMMIT() asm volatile("cp.async.commit_group;" ::: "memory")
#define CP_WAIT0()  asm volatile("cp.async.wait_group 0;" ::: "memory")
#define CP_WAIT1()  asm volatile("cp.async.wait_group 1;" ::: "memory")
#define GROUP_BAR(id) asm volatile("bar.sync %0, 128;" :: "r"(id) : "memory")

static constexpr float SCALE_Q = 0.125f * 1.4426950408889634f;  // 1/sqrt(64)*log2e

// ---------------------------------------------------------------------------
// Kernel 0: W -> fp16 hi, transposed to [n][k] rows, SW128 swizzled.
// Coalesced mapping: lane walks n (contiguous 4B loads within 256B W rows).
// One thread handles one (matrix, n, k-pair): 98304 threads.
// ---------------------------------------------------------------------------
__global__ void prep_w_kernel(const float* __restrict__ Wq,
                              const float* __restrict__ Wk,
                              const float* __restrict__ Wv)
{
    const int th = blockIdx.x * blockDim.x + threadIdx.x;
    if (th >= NCHUNK_ * 8 * 4 * NTOT_) return;
    // th = ((chunk*8 + kg)*4 + jh)*192 + c  -> adjacent threads share k, walk c
    const int c = th % NTOT_;              // 0..191  (n contiguous per matrix)
    const int rest = th / NTOT_;
    const int jh = rest & 3;               // word within 16B group
    const int kgc = rest >> 2;
    const int kg = kgc & 7;
    const int chunk = kgc >> 3;
    const int n = c & 63;
    const float* W = (c < 64) ? Wq : (c < 128) ? Wk : Wv;
    const int k0 = chunk * TK_ + kg * 8 + jh * 2;

    const float a = W[(size_t)k0 * HD_ + n];        // coalesced across lanes
    const float b = W[(size_t)(k0 + 1) * HD_ + n];  // coalesced across lanes
    const size_t base = (size_t)chunk * WTILE_BYTES;
    const uint32_t off = swz128((uint32_t)c * 128u + (uint32_t)kg * 16u) + jh * 4u;
    *(uint32_t*)(g_bhi + base + off) = pack_h2(a, b);
}

// ---------------------------------------------------------------------------
// Kernel 1: QKV projection, mma.sync fp16 1-term, cp.async staged fp32 A.
// (unchanged from R13)
// ---------------------------------------------------------------------------
static constexpr int A32_TILE = 64 * 64 * 4;       // 16384 bytes (fp32)
static constexpr int AH_TILE  = 64 * 128;          // 8192 bytes (fp16)
static constexpr int B_TILE   = NTOT_ * 128;       // 24576 bytes
static constexpr int PROJ_STAGE = A32_TILE + AH_TILE + B_TILE;   // 49152
static constexpr int PROJ_SMEM  = 1024 + 2 * PROJ_STAGE;         // 99328

__global__ __launch_bounds__(256, 2) void proj_mma_kernel(const float* __restrict__ x)
{
    extern __shared__ uint8_t dynsm[];
    const uint32_t raw = smem_u32(dynsm);
    const uint32_t base = (raw + 1023u) & ~1023u;
    uint8_t* const sm = dynsm + (base - raw);

    const int tid = threadIdx.x;
    const int wid = tid >> 5;
    const int lane = tid & 31;
    const size_t row0g = (size_t)blockIdx.x * 64;

    float C[4][3][4];
#pragma unroll
    for (int mt = 0; mt < 4; mt++)
#pragma unroll
        for (int nt = 0; nt < 3; nt++)
#pragma unroll
            for (int e = 0; e < 4; e++) C[mt][nt][e] = 0.0f;

    const uint32_t a_row = (uint32_t)(lane & 15);
    const uint32_t a_kb  = (uint32_t)((lane >> 4) * 16);
    const uint32_t b_row = (uint32_t)(lane & 7);
    const uint32_t b_kb  = (uint32_t)(((lane >> 3) & 1) * 16);

    auto issue = [&](int st, int kc) {
        const uint32_t sb = base + st * PROJ_STAGE;
#pragma unroll
        for (int i = 0; i < 4; i++) {
            const int idx = tid + i * 256;
            const int row = idx >> 4;
            const int c4  = idx & 15;
            cp_async16(sb + idx * 16, &x[(row0g + row) * D_ + kc * TK_ + c4 * 4]);
        }
        const uint8_t* srcH = g_bhi + (size_t)kc * WTILE_BYTES;
#pragma unroll
        for (int i = 0; i < 6; i++) {
            const int idx = tid + i * 256;
            cp_async16(sb + A32_TILE + AH_TILE + idx * 16, srcH + idx * 16);
        }
    };

    issue(0, 0);
    CP_COMMIT();

    for (int kc = 0; kc < NCHUNK_; kc++) {
        const int st = kc & 1;
        if (kc + 1 < NCHUNK_) {
            issue(st ^ 1, kc + 1);
            CP_COMMIT();
            CP_WAIT1();
        } else {
            CP_WAIT0();
        }
        __syncthreads();

        const uint32_t sb = base + st * PROJ_STAGE;
        {
            const float* a32 = (const float*)(sm + st * PROJ_STAGE);
            uint8_t* ah = sm + st * PROJ_STAGE + A32_TILE;
#pragma unroll
            for (int i = 0; i < 4; i++) {
                const int idx = tid + i * 256;
                const int row = idx >> 4;
                const int c4  = idx & 15;
                const float4 v = *(const float4*)&a32[row * 64 + c4 * 4];
                const uint32_t h0 = pack_h2(v.x, v.y);
                const uint32_t h1 = pack_h2(v.z, v.w);
                const uint32_t off = swz128((uint32_t)row * 128u + (uint32_t)c4 * 8u);
                *(uint2*)(ah + off) = make_uint2(h0, h1);
            }
        }
        __syncthreads();

        const uint32_t sAh = sb + A32_TILE;
        const uint32_t sBh = sb + A32_TILE + AH_TILE;

#pragma unroll
        for (int ks = 0; ks < 4; ks++) {
            uint32_t Ah[4][4];
#pragma unroll
            for (int mt = 0; mt < 4; mt++) {
                const uint32_t roff =
                    swz128((uint32_t)(mt * 16 + a_row) * 128u +
                           (uint32_t)ks * 32u + a_kb);
                ldsm_x4(Ah[mt], sAh + roff);
            }
#pragma unroll
            for (int nt = 0; nt < 3; nt++) {
                const uint32_t boff =
                    swz128((uint32_t)(wid * 24 + nt * 8 + b_row) * 128u +
                           (uint32_t)ks * 32u + b_kb);
                uint32_t Bh[2];
                ldsm_x2(Bh, sBh + boff);
#pragma unroll
                for (int mt = 0; mt < 4; mt++) {
                    mma_f16(C[mt][nt], Ah[mt], Bh[0], Bh[1]);
                }
            }
        }
        __syncthreads();
    }

    // Epilogue: qhi (x SCALE_Q), khi, vhi
#pragma unroll
    for (int mt = 0; mt < 4; mt++) {
        const size_t r = row0g + mt * 16 + (lane >> 2);
#pragma unroll
        for (int nt = 0; nt < 3; nt++) {
            const int c = wid * 24 + nt * 8 + 2 * (lane & 3);
            const int n = c & 63;
#pragma unroll
            for (int half = 0; half < 2; half++) {
                const size_t rr = r + half * 8;
                float v0 = C[mt][nt][half * 2 + 0];
                float v1 = C[mt][nt][half * 2 + 1];
                __half* o;
                if (c < 64) {
                    v0 *= SCALE_Q; v1 *= SCALE_Q;
                    o = g_qhi;
                } else {
                    o = (c < 128) ? g_khi : g_vhi;
                }
                *(uint32_t*)&o[rr * HD_ + n] = pack_h2(v0, v1);
            }
        }
    }
}

// ---------------------------------------------------------------------------
// Kernel 2: flash attention, 512-thr CTA = 4 groups of 128, in-CTA merge.
// Q fragments re-loaded per ks step from smem (frees 16 regs vs persistent).
// ---------------------------------------------------------------------------
static constexpr int Q_BYTES   = 64 * 128;          // 8192
static constexpr int KV_STAGE  = 2 * 64 * 128;      // 16384 (khi|vhi)
static constexpr int KV_REGION = 2 * KV_STAGE;      // 32768 per group
static constexpr int ATTN_SMEM = 1024 + Q_BYTES + 4 * KV_REGION;  // 140288

__global__ __launch_bounds__(512, 1) void attn_mma_kernel(float* __restrict__ out)
{
    extern __shared__ uint8_t dynsm[];
    const uint32_t raw = smem_u32(dynsm);
    const uint32_t base = (raw + 1023u) & ~1023u;
    uint8_t* const smp = dynsm + (base - raw);

    const int tid = threadIdx.x;
    const int wid = tid >> 5;
    const int lane = tid & 31;
    const int grp = wid >> 2;             // 0..3
    const int wi  = wid & 3;              // warp within group
    const int gt  = tid & 127;            // thread within group

    const int bid = blockIdx.x;
    const int qt = 31 - (bid >> 3);       // largest work first
    const int b  = bid & 7;

    const int n = qt + 1;
    const int base4 = n >> 2;
    const int rem = n & 3;
    const int kt0 = grp * base4 + (grp < rem ? grp : rem);
    const int niter = base4 + (grp < rem ? 1 : 0);

    const uint32_t sQ  = base;
    const uint32_t sKV = base + Q_BYTES + grp * KV_REGION;
    const size_t qrow0 = (size_t)b * T_ + (size_t)qt * 64;

    // ---- Q via cp.async: 512 threads x 16B ----
    {
        const int row = tid >> 3;
        const int c16 = tid & 7;
        const uint32_t doff = swz128((uint32_t)row * 128u + (uint32_t)c16 * 16u);
        cp_async16(sQ + doff, &g_qhi[(qrow0 + row) * HD_ + c16 * 8]);
    }
    CP_COMMIT();

    auto prefetch_kv = [&](int kt, int stage) {
        const uint32_t sb = sKV + stage * KV_STAGE;
        const size_t krow0 = (size_t)b * T_ + (size_t)kt * 64;
#pragma unroll
        for (int i = 0; i < 8; i++) {
            const int idx = gt + i * 128;      // 0..1023
            const int arr = idx >> 9;          // 0 khi, 1 vhi
            const int row = (idx >> 3) & 63;
            const int c16 = idx & 7;
            const uint32_t doff = swz128((uint32_t)row * 128u + (uint32_t)c16 * 16u);
            const __half* src = arr ? g_vhi : g_khi;
            cp_async16(sb + arr * 8192 + doff, &src[(krow0 + row) * HD_ + c16 * 8]);
        }
    };
    if (niter > 0) prefetch_kv(kt0, 0);
    CP_COMMIT();
    CP_WAIT0();
    __syncthreads();

    // Per-lane Q ldsm address (recomputed cheaply; Q re-loaded per ks step)
    const uint32_t qbase =
        sQ + swz128((uint32_t)(wi * 16 + (lane & 15)) * 128u +
                    (uint32_t)((lane >> 4) * 16));

    float O[8][4];
#pragma unroll
    for (int nh = 0; nh < 8; nh++)
#pragma unroll
        for (int e = 0; e < 4; e++) O[nh][e] = 0.0f;
    float m0 = -1e30f, m1 = -1e30f, l0 = 0.0f, l1 = 0.0f;

    const int kg  = lane >> 3;
    const uint32_t k_row8 = (uint32_t)(lane & 7);
    const uint32_t k_rowsel = (uint32_t)(kg >> 1) * 8;
    const uint32_t k_kb = (uint32_t)(kg & 1) * 16;
    const uint32_t v_rowsel = (uint32_t)(kg & 1) * 8;
    const uint32_t v_colsel = (uint32_t)(kg >> 1) * 16;
    const int q2 = 2 * (lane & 3);
    const int rloc = (lane >> 2);

    for (int i = 0; i < niter; i++) {
        if (i + 1 < niter) prefetch_kv(kt0 + i + 1, (i + 1) & 1);
        CP_COMMIT();

        const int kt = kt0 + i;
        const uint32_t sb = sKV + (i & 1) * KV_STAGE;
        const uint32_t sKh = sb;
        const uint32_t sVh = sb + 8192;

        // ---- S = Q @ K^T (Q fragment loaded per ks; swizzle XOR walks kb) ----
        float S[8][4];
#pragma unroll
        for (int nt = 0; nt < 8; nt++)
#pragma unroll
            for (int e = 0; e < 4; e++) S[nt][e] = 0.0f;

#pragma unroll
        for (int ks = 0; ks < 4; ks++) {
            uint32_t Qf[4];
            ldsm_x4(Qf, qbase ^ (uint32_t)(ks * 32));
#pragma unroll
            for (int ntp = 0; ntp < 4; ntp++) {
                const uint32_t boff =
                    swz128((uint32_t)(ntp * 16 + k_rowsel + k_row8) * 128u +
                           (uint32_t)ks * 32u + k_kb);
                uint32_t Kf[4];
                ldsm_x4(Kf, sKh + boff);
                mma_f16(S[2 * ntp],     Qf, Kf[0], Kf[1]);
                mma_f16(S[2 * ntp + 1], Qf, Kf[2], Kf[3]);
            }
        }

        // ---- causal mask on diagonal tile ----
        if (kt == qt) {
            const int r0 = wi * 16 + rloc;
#pragma unroll
            for (int nt = 0; nt < 8; nt++) {
                const int c0 = nt * 8 + q2;
                if (c0 > r0)     S[nt][0] = -1e30f;
                if (c0 + 1 > r0) S[nt][1] = -1e30f;
                if (c0 > r0 + 8)     S[nt][2] = -1e30f;
                if (c0 + 1 > r0 + 8) S[nt][3] = -1e30f;
            }
        }

        // ---- online softmax (base-2), P in fp16x2 ----
        float mx0 = -1e30f, mx1 = -1e30f;
#pragma unroll
        for (int nt = 0; nt < 8; nt++) {
            mx0 = fmaxf(mx0, fmaxf(S[nt][0], S[nt][1]));
            mx1 = fmaxf(mx1, fmaxf(S[nt][2], S[nt][3]));
        }
        mx0 = fmaxf(mx0, __shfl_xor_sync(0xffffffffu, mx0, 1));
        mx0 = fmaxf(mx0, __shfl_xor_sync(0xffffffffu, mx0, 2));
        mx1 = fmaxf(mx1, __shfl_xor_sync(0xffffffffu, mx1, 1));
        mx1 = fmaxf(mx1, __shfl_xor_sync(0xffffffffu, mx1, 2));
        const float mn0 = fmaxf(m0, mx0);
        const float mn1 = fmaxf(m1, mx1);
        const float a0 = ex2f(m0 - mn0);
        const float a1 = ex2f(m1 - mn1);
        m0 = mn0; m1 = mn1;

        uint32_t P[4][4];
        float sum0 = 0.0f, sum1 = 0.0f;
#pragma unroll
        for (int nt = 0; nt < 8; nt++) {
            const uint32_t w01 = ex2h2(f2h2(S[nt][0] - mn0, S[nt][1] - mn0));
            const uint32_t w23 = ex2h2(f2h2(S[nt][2] - mn1, S[nt][3] - mn1));
            P[nt >> 1][(nt & 1) * 2 + 0] = w01;
            P[nt >> 1][(nt & 1) * 2 + 1] = w23;
            const float2 f01 = h22f2(w01);
            const float2 f23 = h22f2(w23);
            sum0 += f01.x + f01.y;
            sum1 += f23.x + f23.y;
        }
        sum0 += __shfl_xor_sync(0xffffffffu, sum0, 1);
        sum0 += __shfl_xor_sync(0xffffffffu, sum0, 2);
        sum1 += __shfl_xor_sync(0xffffffffu, sum1, 1);
        sum1 += __shfl_xor_sync(0xffffffffu, sum1, 2);
        l0 = l0 * a0 + sum0;
        l1 = l1 * a1 + sum1;

#pragma unroll
        for (int nh = 0; nh < 8; nh++) {
            O[nh][0] *= a0; O[nh][1] *= a0;
            O[nh][2] *= a1; O[nh][3] *= a1;
        }

        // ---- O += P @ V ----
#pragma unroll
        for (int t = 0; t < 4; t++) {
#pragma unroll
            for (int nhp = 0; nhp < 4; nhp++) {
                const uint32_t voff =
                    swz128((uint32_t)(t * 16 + v_rowsel + k_row8) * 128u +
                           (uint32_t)nhp * 32u + v_colsel);
                uint32_t Vf[4];
                ldsm_x4_trans(Vf, sVh + voff);
                mma_f16(O[2 * nhp],     P[t], Vf[0], Vf[1]);
                mma_f16(O[2 * nhp + 1], P[t], Vf[2], Vf[3]);
            }
        }

        CP_WAIT0();
        GROUP_BAR(1 + grp);
    }

    // ---- in-CTA merge: groups 1-3 stash partials in their KV regions ----
    if (grp != 0) {
        float* const mO  = (float*)(smp + Q_BYTES + grp * KV_REGION);
        float* const mML = (float*)(smp + Q_BYTES + grp * KV_REGION + 16896);
#pragma unroll
        for (int nh = 0; nh < 8; nh++)
#pragma unroll
            for (int e = 0; e < 4; e++) mO[gt * 33 + nh * 4 + e] = O[nh][e];
        mML[gt * 4 + 0] = m0;
        mML[gt * 4 + 1] = l0;
        mML[gt * 4 + 2] = m1;
        mML[gt * 4 + 3] = l1;
    }
    __syncthreads();

    if (grp == 0) {
        float pm0[3], pl0[3], pm1[3], pl1[3];
        float M0 = m0, M1 = m1;
#pragma unroll
        for (int g = 0; g < 3; g++) {
            const float* mML = (const float*)(smp + Q_BYTES + (g + 1) * KV_REGION + 16896);
            pm0[g] = mML[gt * 4 + 0];
            pl0[g] = mML[gt * 4 + 1];
            pm1[g] = mML[gt * 4 + 2];
            pl1[g] = mML[gt * 4 + 3];
            M0 = fmaxf(M0, pm0[g]);
            M1 = fmaxf(M1, pm1[g]);
        }
        const float a0 = ex2f(m0 - M0);
        const float a1 = ex2f(m1 - M1);
        float pa0[3], pa1[3];
        float L0 = l0 * a0, L1 = l1 * a1;
#pragma unroll
        for (int g = 0; g < 3; g++) {
            pa0[g] = ex2f(pm0[g] - M0);
            pa1[g] = ex2f(pm1[g] - M1);
            L0 += pl0[g] * pa0[g];
            L1 += pl1[g] * pa1[g];
        }
        const float il0 = 1.0f / L0;
        const float il1 = 1.0f / L1;

        const int row0 = wi * 16 + rloc;
        const size_t grow = qrow0 + (size_t)row0;
#pragma unroll
        for (int nh = 0; nh < 8; nh++) {
            const int hcol = nh * 8 + q2;
            float o0 = O[nh][0] * a0;
            float o1 = O[nh][1] * a0;
            float o2 = O[nh][2] * a1;
            float o3 = O[nh][3] * a1;
#pragma unroll
            for (int g = 0; g < 3; g++) {
                const float* mO = (const float*)(smp + Q_BYTES + (g + 1) * KV_REGION);
                o0 += mO[gt * 33 + nh * 4 + 0] * pa0[g];
                o1 += mO[gt * 33 + nh * 4 + 1] * pa0[g];
                o2 += mO[gt * 33 + nh * 4 + 2] * pa1[g];
                o3 += mO[gt * 33 + nh * 4 + 3] * pa1[g];
            }
            *(float2*)&out[grow * HD_ + hcol] = make_float2(o0 * il0, o1 * il0);
            *(float2*)&out[(grow + 8) * HD_ + hcol] = make_float2(o2 * il1, o3 * il1);
        }
    }
}

// ---------------------------------------------------------------------------
extern "C" void kernel_launch(void* const* d_in, const int* in_sizes, int n_in,
                              void* d_out, int out_size)
{
    const float* x  = (const float*)d_in[0];
    const float* Wq = (const float*)d_in[1];
    const float* Wk = (const float*)d_in[2];
    const float* Wv = (const float*)d_in[3];
    float* out = (float*)d_out;

    cudaFuncSetAttribute(proj_mma_kernel,
                         cudaFuncAttributeMaxDynamicSharedMemorySize, PROJ_SMEM);
    cudaFuncSetAttribute(attn_mma_kernel,
                         cudaFuncAttributeMaxDynamicSharedMemorySize, ATTN_SMEM);

    const int prep_threads = NCHUNK_ * 8 * 4 * NTOT_;
    prep_w_kernel<<<(prep_threads + 255) / 256, 256>>>(Wq, Wk, Wv);
    proj_mma_kernel<<<M_ / 64, 256, PROJ_SMEM>>>(x);
    attn_mma_kernel<<<256, 512, ATTN_SMEM>>>(out);
}

// round 15
// speedup vs baseline: 1.1789x; 1.0149x over previous
#include <cuda_runtime.h>
#include <cuda_fp16.h>
#include <cstdint>

// Problem constants
static constexpr int B_  = 8;
static constexpr int T_  = 2048;
static constexpr int D_  = 1024;
static constexpr int HD_ = 64;
static constexpr int M_  = B_ * T_;       // 16384 rows
static constexpr int NTOT_ = 192;         // q|k|v fused output columns
static constexpr int TK_ = 64;            // K per chunk (128B fp16 rows)
static constexpr int NCHUNK_ = D_ / TK_;  // 16

// Device-global scratch (fp16 hi-only; q pre-scaled by 0.125*log2e).
__device__ __align__(16) __half g_qhi[(size_t)M_ * HD_];
__device__ __align__(16) __half g_khi[(size_t)M_ * HD_];
__device__ __align__(16) __half g_vhi[(size_t)M_ * HD_];
// Pre-transposed + swizzled fp16 W-hi tiles: [chunk][n=0..191][k=0..63]
static constexpr size_t WTILE_BYTES = (size_t)NTOT_ * 128;   // 24576 per chunk
__device__ __align__(16) uint8_t g_bhi[(size_t)NCHUNK_ * WTILE_BYTES];

__host__ __device__ __forceinline__ uint32_t swz128(uint32_t off) {
    return off ^ ((off >> 3) & 0x70);
}
__device__ __forceinline__ uint32_t smem_u32(const void* p) {
    uint32_t a;
    asm("{ .reg .u64 t; cvta.to.shared.u64 t, %1; cvt.u32.u64 %0, t; }"
        : "=r"(a) : "l"(p));
    return a;
}
__device__ __forceinline__ void ldsm_x4(uint32_t (&r)[4], uint32_t addr) {
    asm volatile("ldmatrix.sync.aligned.m8n8.x4.shared.b16 {%0,%1,%2,%3}, [%4];"
                 : "=r"(r[0]), "=r"(r[1]), "=r"(r[2]), "=r"(r[3]) : "r"(addr));
}
__device__ __forceinline__ void ldsm_x2(uint32_t (&r)[2], uint32_t addr) {
    asm volatile("ldmatrix.sync.aligned.m8n8.x2.shared.b16 {%0,%1}, [%2];"
                 : "=r"(r[0]), "=r"(r[1]) : "r"(addr));
}
__device__ __forceinline__ void ldsm_x4_trans(uint32_t (&r)[4], uint32_t addr) {
    asm volatile("ldmatrix.sync.aligned.m8n8.x4.trans.shared.b16 {%0,%1,%2,%3}, [%4];"
                 : "=r"(r[0]), "=r"(r[1]), "=r"(r[2]), "=r"(r[3]) : "r"(addr));
}
__device__ __forceinline__ void mma_f16(float (&d)[4], const uint32_t (&a)[4],
                                        uint32_t b0, uint32_t b1) {
    asm volatile(
        "mma.sync.aligned.m16n8k16.row.col.f32.f16.f16.f32 "
        "{%0,%1,%2,%3}, {%4,%5,%6,%7}, {%8,%9}, {%0,%1,%2,%3};"
        : "+f"(d[0]), "+f"(d[1]), "+f"(d[2]), "+f"(d[3])
        : "r"(a[0]), "r"(a[1]), "r"(a[2]), "r"(a[3]), "r"(b0), "r"(b1));
}
__device__ __forceinline__ uint32_t pack_h2(float lo, float hi) {
    __half l = __float2half_rn(lo);
    __half h = __float2half_rn(hi);
    return ((uint32_t)__half_as_ushort(h) << 16) | __half_as_ushort(l);
}
__device__ __forceinline__ uint32_t f2h2(float lo, float hi) {
    uint32_t r;
    asm("cvt.rn.f16x2.f32 %0, %1, %2;" : "=r"(r) : "f"(hi), "f"(lo));
    return r;
}
__device__ __forceinline__ uint32_t ex2h2(uint32_t x) {
    uint32_t r;
    asm("ex2.approx.f16x2 %0, %1;" : "=r"(r) : "r"(x));
    return r;
}
__device__ __forceinline__ uint32_t hmax2(uint32_t a, uint32_t b) {
    uint32_t r;
    asm("max.f16x2 %0, %1, %2;" : "=r"(r) : "r"(a), "r"(b));
    return r;
}
__device__ __forceinline__ float2 h22f2(uint32_t w) {
    __half2 h;
    *(uint32_t*)&h = w;
    return __half22float2(h);
}
__device__ __forceinline__ float ex2f(float x) {
    float y;
    asm("ex2.approx.ftz.f32 %0, %1;" : "=f"(y) : "f"(x));
    return y;
}
__device__ __forceinline__ void cp_async16(uint32_t dst, const void* src) {
    asm volatile("cp.async.ca.shared.global [%0], [%1], 16;"
                 :: "r"(dst), "l"(src));
}
#define CP_COMMIT() asm volatile("cp.async.commit_group;" ::: "memory")
#define CP_WAIT0()  asm volatile("cp.async.wait_group 0;" ::: "memory")
#define CP_WAIT1()  asm volatile("cp.async.wait_group 1;" ::: "memory")
#define GROUP_BAR(id) asm volatile("bar.sync %0, 128;" :: "r"(id) : "memory")

static constexpr float SCALE_Q = 0.125f * 1.4426950408889634f;  // 1/sqrt(64)*log2e

// ---------------------------------------------------------------------------
// Kernel 0: W -> fp16 hi, transposed to [n][k] rows, SW128 swizzled.
// ---------------------------------------------------------------------------
__global__ void prep_w_kernel(const float* __restrict__ Wq,
                              const float* __restrict__ Wk,
                              const float* __restrict__ Wv)
{
    const int th = blockIdx.x * blockDim.x + threadIdx.x;
    if (th >= NCHUNK_ * 8 * 4 * NTOT_) return;
    const int c = th % NTOT_;
    const int rest = th / NTOT_;
    const int jh = rest & 3;
    const int kgc = rest >> 2;
    const int kg = kgc & 7;
    const int chunk = kgc >> 3;
    const int n = c & 63;
    const float* W = (c < 64) ? Wq : (c < 128) ? Wk : Wv;
    const int k0 = chunk * TK_ + kg * 8 + jh * 2;

    const float a = W[(size_t)k0 * HD_ + n];
    const float b = W[(size_t)(k0 + 1) * HD_ + n];
    const size_t base = (size_t)chunk * WTILE_BYTES;
    const uint32_t off = swz128((uint32_t)c * 128u + (uint32_t)kg * 16u) + jh * 4u;
    *(uint32_t*)(g_bhi + base + off) = pack_h2(a, b);
}

// ---------------------------------------------------------------------------
// Kernel 1: QKV projection, mma.sync fp16 1-term. (unchanged — at MMA wall)
// ---------------------------------------------------------------------------
static constexpr int A32_TILE = 64 * 64 * 4;
static constexpr int AH_TILE  = 64 * 128;
static constexpr int B_TILE   = NTOT_ * 128;
static constexpr int PROJ_STAGE = A32_TILE + AH_TILE + B_TILE;
static constexpr int PROJ_SMEM  = 1024 + 2 * PROJ_STAGE;

__global__ __launch_bounds__(256, 2) void proj_mma_kernel(const float* __restrict__ x)
{
    extern __shared__ uint8_t dynsm[];
    const uint32_t raw = smem_u32(dynsm);
    const uint32_t base = (raw + 1023u) & ~1023u;
    uint8_t* const sm = dynsm + (base - raw);

    const int tid = threadIdx.x;
    const int wid = tid >> 5;
    const int lane = tid & 31;
    const size_t row0g = (size_t)blockIdx.x * 64;

    float C[4][3][4];
#pragma unroll
    for (int mt = 0; mt < 4; mt++)
#pragma unroll
        for (int nt = 0; nt < 3; nt++)
#pragma unroll
            for (int e = 0; e < 4; e++) C[mt][nt][e] = 0.0f;

    const uint32_t a_row = (uint32_t)(lane & 15);
    const uint32_t a_kb  = (uint32_t)((lane >> 4) * 16);
    const uint32_t b_row = (uint32_t)(lane & 7);
    const uint32_t b_kb  = (uint32_t)(((lane >> 3) & 1) * 16);

    auto issue = [&](int st, int kc) {
        const uint32_t sb = base + st * PROJ_STAGE;
#pragma unroll
        for (int i = 0; i < 4; i++) {
            const int idx = tid + i * 256;
            const int row = idx >> 4;
            const int c4  = idx & 15;
            cp_async16(sb + idx * 16, &x[(row0g + row) * D_ + kc * TK_ + c4 * 4]);
        }
        const uint8_t* srcH = g_bhi + (size_t)kc * WTILE_BYTES;
#pragma unroll
        for (int i = 0; i < 6; i++) {
            const int idx = tid + i * 256;
            cp_async16(sb + A32_TILE + AH_TILE + idx * 16, srcH + idx * 16);
        }
    };

    issue(0, 0);
    CP_COMMIT();

    for (int kc = 0; kc < NCHUNK_; kc++) {
        const int st = kc & 1;
        if (kc + 1 < NCHUNK_) {
            issue(st ^ 1, kc + 1);
            CP_COMMIT();
            CP_WAIT1();
        } else {
            CP_WAIT0();
        }
        __syncthreads();

        const uint32_t sb = base + st * PROJ_STAGE;
        {
            const float* a32 = (const float*)(sm + st * PROJ_STAGE);
            uint8_t* ah = sm + st * PROJ_STAGE + A32_TILE;
#pragma unroll
            for (int i = 0; i < 4; i++) {
                const int idx = tid + i * 256;
                const int row = idx >> 4;
                const int c4  = idx & 15;
                const float4 v = *(const float4*)&a32[row * 64 + c4 * 4];
                const uint32_t h0 = pack_h2(v.x, v.y);
                const uint32_t h1 = pack_h2(v.z, v.w);
                const uint32_t off = swz128((uint32_t)row * 128u + (uint32_t)c4 * 8u);
                *(uint2*)(ah + off) = make_uint2(h0, h1);
            }
        }
        __syncthreads();

        const uint32_t sAh = sb + A32_TILE;
        const uint32_t sBh = sb + A32_TILE + AH_TILE;

#pragma unroll
        for (int ks = 0; ks < 4; ks++) {
            uint32_t Ah[4][4];
#pragma unroll
            for (int mt = 0; mt < 4; mt++) {
                const uint32_t roff =
                    swz128((uint32_t)(mt * 16 + a_row) * 128u +
                           (uint32_t)ks * 32u + a_kb);
                ldsm_x4(Ah[mt], sAh + roff);
            }
#pragma unroll
            for (int nt = 0; nt < 3; nt++) {
                const uint32_t boff =
                    swz128((uint32_t)(wid * 24 + nt * 8 + b_row) * 128u +
                           (uint32_t)ks * 32u + b_kb);
                uint32_t Bh[2];
                ldsm_x2(Bh, sBh + boff);
#pragma unroll
                for (int mt = 0; mt < 4; mt++) {
                    mma_f16(C[mt][nt], Ah[mt], Bh[0], Bh[1]);
                }
            }
        }
        __syncthreads();
    }

#pragma unroll
    for (int mt = 0; mt < 4; mt++) {
        const size_t r = row0g + mt * 16 + (lane >> 2);
#pragma unroll
        for (int nt = 0; nt < 3; nt++) {
            const int c = wid * 24 + nt * 8 + 2 * (lane & 3);
            const int n = c & 63;
#pragma unroll
            for (int half = 0; half < 2; half++) {
                const size_t rr = r + half * 8;
                float v0 = C[mt][nt][half * 2 + 0];
                float v1 = C[mt][nt][half * 2 + 1];
                __half* o;
                if (c < 64) {
                    v0 *= SCALE_Q; v1 *= SCALE_Q;
                    o = g_qhi;
                } else {
                    o = (c < 128) ? g_khi : g_vhi;
                }
                *(uint32_t*)&o[rr * HD_ + n] = pack_h2(v0, v1);
            }
        }
    }
}

// ---------------------------------------------------------------------------
// Kernel 2: flash attention, 512-thr CTA = 4 groups of 128, in-CTA merge.
// Softmax: packed fp16x2 max butterfly (2 shfl), deferred lane-local l,
// O-rescale skip when max unchanged, group phase-skew.
// ---------------------------------------------------------------------------
static constexpr int Q_BYTES   = 64 * 128;
static constexpr int KV_STAGE  = 2 * 64 * 128;
static constexpr int KV_REGION = 2 * KV_STAGE;
static constexpr int ATTN_SMEM = 1024 + Q_BYTES + 4 * KV_REGION;  // 140288

__global__ __launch_bounds__(512, 1) void attn_mma_kernel(float* __restrict__ out)
{
    extern __shared__ uint8_t dynsm[];
    const uint32_t raw = smem_u32(dynsm);
    const uint32_t base = (raw + 1023u) & ~1023u;
    uint8_t* const smp = dynsm + (base - raw);

    const int tid = threadIdx.x;
    const int wid = tid >> 5;
    const int lane = tid & 31;
    const int grp = wid >> 2;
    const int wi  = wid & 3;
    const int gt  = tid & 127;

    const int bid = blockIdx.x;
    const int qt = 31 - (bid >> 3);
    const int b  = bid & 7;

    const int n = qt + 1;
    const int base4 = n >> 2;
    const int rem = n & 3;
    const int kt0 = grp * base4 + (grp < rem ? grp : rem);
    const int niter = base4 + (grp < rem ? 1 : 0);

    const uint32_t sQ  = base;
    const uint32_t sKV = base + Q_BYTES + grp * KV_REGION;
    const size_t qrow0 = (size_t)b * T_ + (size_t)qt * 64;

    // ---- Q via cp.async ----
    {
        const int row = tid >> 3;
        const int c16 = tid & 7;
        const uint32_t doff = swz128((uint32_t)row * 128u + (uint32_t)c16 * 16u);
        cp_async16(sQ + doff, &g_qhi[(qrow0 + row) * HD_ + c16 * 8]);
    }
    CP_COMMIT();

    auto prefetch_kv = [&](int kt, int stage) {
        const uint32_t sb = sKV + stage * KV_STAGE;
        const size_t krow0 = (size_t)b * T_ + (size_t)kt * 64;
#pragma unroll
        for (int i = 0; i < 8; i++) {
            const int idx = gt + i * 128;
            const int arr = idx >> 9;
            const int row = (idx >> 3) & 63;
            const int c16 = idx & 7;
            const uint32_t doff = swz128((uint32_t)row * 128u + (uint32_t)c16 * 16u);
            const __half* src = arr ? g_vhi : g_khi;
            cp_async16(sb + arr * 8192 + doff, &src[(krow0 + row) * HD_ + c16 * 8]);
        }
    };
    if (niter > 0) prefetch_kv(kt0, 0);
    CP_COMMIT();
    CP_WAIT0();
    __syncthreads();

    // ---- phase skew: dependent FMA chain ~85 cyc per grp step ----
    {
        float z = 1.0f + (float)tid * 1e-30f;
#pragma unroll 1
        for (int it = 0; it < grp * 20; it++)
            z = fmaf(z, 1.0000001f, 1e-33f);
        if (z == 12345.678f) out[0] = z;   // never true; keeps chain alive
    }

    const uint32_t qbase =
        sQ + swz128((uint32_t)(wi * 16 + (lane & 15)) * 128u +
                    (uint32_t)((lane >> 4) * 16));

    float O[8][4];
#pragma unroll
    for (int nh = 0; nh < 8; nh++)
#pragma unroll
        for (int e = 0; e < 4; e++) O[nh][e] = 0.0f;
    float m0 = -1e30f, m1 = -1e30f;
    float l0 = 0.0f, l1 = 0.0f;       // per-lane partials; reduced after loop

    const int kg  = lane >> 3;
    const uint32_t k_row8 = (uint32_t)(lane & 7);
    const uint32_t k_rowsel = (uint32_t)(kg >> 1) * 8;
    const uint32_t k_kb = (uint32_t)(kg & 1) * 16;
    const uint32_t v_rowsel = (uint32_t)(kg & 1) * 8;
    const uint32_t v_colsel = (uint32_t)(kg >> 1) * 16;
    const int q2 = 2 * (lane & 3);
    const int rloc = (lane >> 2);

    for (int i = 0; i < niter; i++) {
        if (i + 1 < niter) prefetch_kv(kt0 + i + 1, (i + 1) & 1);
        CP_COMMIT();

        const int kt = kt0 + i;
        const uint32_t sb = sKV + (i & 1) * KV_STAGE;
        const uint32_t sKh = sb;
        const uint32_t sVh = sb + 8192;

        // ---- S = Q @ K^T ----
        float S[8][4];
#pragma unroll
        for (int nt = 0; nt < 8; nt++)
#pragma unroll
            for (int e = 0; e < 4; e++) S[nt][e] = 0.0f;

#pragma unroll
        for (int ks = 0; ks < 4; ks++) {
            uint32_t Qf[4];
            ldsm_x4(Qf, qbase ^ (uint32_t)(ks * 32));
#pragma unroll
            for (int ntp = 0; ntp < 4; ntp++) {
                const uint32_t boff =
                    swz128((uint32_t)(ntp * 16 + k_rowsel + k_row8) * 128u +
                           (uint32_t)ks * 32u + k_kb);
                uint32_t Kf[4];
                ldsm_x4(Kf, sKh + boff);
                mma_f16(S[2 * ntp],     Qf, Kf[0], Kf[1]);
                mma_f16(S[2 * ntp + 1], Qf, Kf[2], Kf[3]);
            }
        }

        // ---- causal mask on diagonal tile ----
        if (kt == qt) {
            const int r0 = wi * 16 + rloc;
#pragma unroll
            for (int nt = 0; nt < 8; nt++) {
                const int c0 = nt * 8 + q2;
                if (c0 > r0)     S[nt][0] = -1e30f;
                if (c0 + 1 > r0) S[nt][1] = -1e30f;
                if (c0 > r0 + 8)     S[nt][2] = -1e30f;
                if (c0 + 1 > r0 + 8) S[nt][3] = -1e30f;
            }
        }

        // ---- online softmax: packed fp16x2 max butterfly ----
        float mx0 = -1e30f, mx1 = -1e30f;
#pragma unroll
        for (int nt = 0; nt < 8; nt++) {
            mx0 = fmaxf(mx0, fmaxf(S[nt][0], S[nt][1]));
            mx1 = fmaxf(mx1, fmaxf(S[nt][2], S[nt][3]));
        }
        uint32_t mxp = f2h2(mx0, mx1);
        mxp = hmax2(mxp, __shfl_xor_sync(0xffffffffu, mxp, 1));
        mxp = hmax2(mxp, __shfl_xor_sync(0xffffffffu, mxp, 2));
        const float2 mxf = h22f2(mxp);
        const float mn0 = fmaxf(m0, mxf.x);
        const float mn1 = fmaxf(m1, mxf.y);
        const float a0 = ex2f(m0 - mn0);
        const float a1 = ex2f(m1 - mn1);
        m0 = mn0; m1 = mn1;

        uint32_t P[4][4];
        float sum0 = 0.0f, sum1 = 0.0f;
#pragma unroll
        for (int nt = 0; nt < 8; nt++) {
            const uint32_t w01 = ex2h2(f2h2(S[nt][0] - mn0, S[nt][1] - mn0));
            const uint32_t w23 = ex2h2(f2h2(S[nt][2] - mn1, S[nt][3] - mn1));
            P[nt >> 1][(nt & 1) * 2 + 0] = w01;
            P[nt >> 1][(nt & 1) * 2 + 1] = w23;
            const float2 f01 = h22f2(w01);
            const float2 f23 = h22f2(w23);
            sum0 += f01.x + f01.y;
            sum1 += f23.x + f23.y;
        }
        // lane-local l update (cross-lane reduction deferred to after loop)
        l0 = l0 * a0 + sum0;
        l1 = l1 * a1 + sum1;

        if (!(a0 == 1.0f && a1 == 1.0f)) {
#pragma unroll
            for (int nh = 0; nh < 8; nh++) {
                O[nh][0] *= a0; O[nh][1] *= a0;
                O[nh][2] *= a1; O[nh][3] *= a1;
            }
        }

        // ---- O += P @ V ----
#pragma unroll
        for (int t = 0; t < 4; t++) {
#pragma unroll
            for (int nhp = 0; nhp < 4; nhp++) {
                const uint32_t voff =
                    swz128((uint32_t)(t * 16 + v_rowsel + k_row8) * 128u +
                           (uint32_t)nhp * 32u + v_colsel);
                uint32_t Vf[4];
                ldsm_x4_trans(Vf, sVh + voff);
                mma_f16(O[2 * nhp],     P[t], Vf[0], Vf[1]);
                mma_f16(O[2 * nhp + 1], P[t], Vf[2], Vf[3]);
            }
        }

        CP_WAIT0();
        GROUP_BAR(1 + grp);
    }

    // ---- finalize per-row l (cross-lane quad reduction, once) ----
    l0 += __shfl_xor_sync(0xffffffffu, l0, 1);
    l0 += __shfl_xor_sync(0xffffffffu, l0, 2);
    l1 += __shfl_xor_sync(0xffffffffu, l1, 1);
    l1 += __shfl_xor_sync(0xffffffffu, l1, 2);

    // ---- in-CTA merge: groups 1-3 stash partials ----
    if (grp != 0) {
        float* const mO  = (float*)(smp + Q_BYTES + grp * KV_REGION);
        float* const mML = (float*)(smp + Q_BYTES + grp * KV_REGION + 16896);
#pragma unroll
        for (int nh = 0; nh < 8; nh++)
#pragma unroll
            for (int e = 0; e < 4; e++) mO[gt * 33 + nh * 4 + e] = O[nh][e];
        mML[gt * 4 + 0] = m0;
        mML[gt * 4 + 1] = l0;
        mML[gt * 4 + 2] = m1;
        mML[gt * 4 + 3] = l1;
    }
    __syncthreads();

    if (grp == 0) {
        float pm0[3], pl0[3], pm1[3], pl1[3];
        float M0 = m0, M1 = m1;
#pragma unroll
        for (int g = 0; g < 3; g++) {
            const float* mML = (const float*)(smp + Q_BYTES + (g + 1) * KV_REGION + 16896);
            pm0[g] = mML[gt * 4 + 0];
            pl0[g] = mML[gt * 4 + 1];
            pm1[g] = mML[gt * 4 + 2];
            pl1[g] = mML[gt * 4 + 3];
            M0 = fmaxf(M0, pm0[g]);
            M1 = fmaxf(M1, pm1[g]);
        }
        const float a0 = ex2f(m0 - M0);
        const float a1 = ex2f(m1 - M1);
        float pa0[3], pa1[3];
        float L0 = l0 * a0, L1 = l1 * a1;
#pragma unroll
        for (int g = 0; g < 3; g++) {
            pa0[g] = ex2f(pm0[g] - M0);
            pa1[g] = ex2f(pm1[g] - M1);
            L0 += pl0[g] * pa0[g];
            L1 += pl1[g] * pa1[g];
        }
        const float il0 = 1.0f / L0;
        const float il1 = 1.0f / L1;

        const int row0 = wi * 16 + rloc;
        const size_t grow = qrow0 + (size_t)row0;
#pragma unroll
        for (int nh = 0; nh < 8; nh++) {
            const int hcol = nh * 8 + q2;
            float o0 = O[nh][0] * a0;
            float o1 = O[nh][1] * a0;
            float o2 = O[nh][2] * a1;
            float o3 = O[nh][3] * a1;
#pragma unroll
            for (int g = 0; g < 3; g++) {
                const float* mO = (const float*)(smp + Q_BYTES + (g + 1) * KV_REGION);
                o0 += mO[gt * 33 + nh * 4 + 0] * pa0[g];
                o1 += mO[gt * 33 + nh * 4 + 1] * pa0[g];
                o2 += mO[gt * 33 + nh * 4 + 2] * pa1[g];
                o3 += mO[gt * 33 + nh * 4 + 3] * pa1[g];
            }
            *(float2*)&out[grow * HD_ + hcol] = make_float2(o0 * il0, o1 * il0);
            *(float2*)&out[(grow + 8) * HD_ + hcol] = make_float2(o2 * il1, o3 * il1);
        }
    }
}

// ---------------------------------------------------------------------------
extern "C" void kernel_launch(void* const* d_in, const int* in_sizes, int n_in,
                              void* d_out, int out_size)
{
    const float* x  = (const float*)d_in[0];
    const float* Wq = (const float*)d_in[1];
    const float* Wk = (const float*)d_in[2];
    const float* Wv = (const float*)d_in[3];
    float* out = (float*)d_out;

    cudaFuncSetAttribute(proj_mma_kernel,
                         cudaFuncAttributeMaxDynamicSharedMemorySize, PROJ_SMEM);
    cudaFuncSetAttribute(attn_mma_kernel,
                         cudaFuncAttributeMaxDynamicSharedMemorySize, ATTN_SMEM);

    const int prep_threads = NCHUNK_ * 8 * 4 * NTOT_;
    prep_w_kernel<<<(prep_threads + 255) / 256, 256>>>(Wq, Wk, Wv);
    proj_mma_kernel<<<M_ / 64, 256, PROJ_SMEM>>>(x);
    attn_mma_kernel<<<256, 512, ATTN_SMEM>>>(out);
}